// round 2
// baseline (speedup 1.0000x reference)
#include <cuda_runtime.h>
#include <cuda_bf16.h>
#include <cstdint>

// Problem constants
#define NB 2
#define HH 16
#define TT 2048
#define DD 1024
#define SS 64
#define NEG_INF (-1e9f)

// Scratch (device globals -> allowed; no runtime allocation)
__device__ float g_Q[NB * HH * TT * SS];   // [n][h][t][s]
__device__ float g_K[NB * HH * TT * SS];   // [n][h][t][s]
__device__ float g_V[NB * HH * TT * SS];   // [n][h][t][s]
__device__ float g_O[NB * TT * DD];        // [n][t][h*64+s]

__device__ __forceinline__ uint32_t f2tf32(float x) {
    uint32_t r;
    asm("cvt.rna.tf32.f32 %0, %1;" : "=r"(r) : "f"(x));
    return r;
}

__device__ __forceinline__ void mma_tf32(float* c, const uint32_t* a, uint32_t b0, uint32_t b1) {
    asm volatile(
        "mma.sync.aligned.m16n8k8.row.col.f32.tf32.tf32.f32 "
        "{%0,%1,%2,%3}, {%4,%5,%6,%7}, {%8,%9}, {%0,%1,%2,%3};\n"
        : "+f"(c[0]), "+f"(c[1]), "+f"(c[2]), "+f"(c[3])
        : "r"(a[0]), "r"(a[1]), "r"(a[2]), "r"(a[3]), "r"(b0), "r"(b1));
}

// ============================================================================
// TF32 GEMM: C[M,1024] = A[M,1024] * B[1024,1024], row-major.
// csel 0/1/2 -> scatter into g_Q/g_K/g_V head-major layout (with scale),
// csel 3     -> plain row-major into Cext.
// asel 1     -> A = g_O (output projection).
// ============================================================================
__global__ void __launch_bounds__(256) gemm_tf32_kernel(
    const float* __restrict__ Aext, const float* __restrict__ B,
    float* __restrict__ Cext, int asel, int csel, float scale)
{
    constexpr int BM = 128, BN = 128, BK = 16;
    __shared__ uint32_t As[BK][BM + 4];
    __shared__ uint32_t Bs[BK][BN + 4];

    const float* A = asel ? g_O : Aext;
    float* C = (csel == 0) ? g_Q : (csel == 1) ? g_K : (csel == 2) ? g_V : Cext;

    const int tid = threadIdx.x;
    const int lane = tid & 31, warp = tid >> 5;
    const int wm = warp & 3, wn = warp >> 2;           // 4 x 2 warp grid
    const int m0 = blockIdx.y * BM, n0 = blockIdx.x * BN;

    float c[2][8][4];
#pragma unroll
    for (int mt = 0; mt < 2; mt++)
#pragma unroll
        for (int nt = 0; nt < 8; nt++)
#pragma unroll
            for (int i = 0; i < 4; i++) c[mt][nt][i] = 0.f;

    for (int k0 = 0; k0 < 1024; k0 += BK) {
        // Load A tile (128x16) transposed into As[k][m]
#pragma unroll
        for (int i = 0; i < 2; i++) {
            int lin = tid + i * 256;
            int r = lin >> 2, c4 = lin & 3;
            float4 v = *(const float4*)(A + (size_t)(m0 + r) * 1024 + k0 + c4 * 4);
            As[c4 * 4 + 0][r] = f2tf32(v.x);
            As[c4 * 4 + 1][r] = f2tf32(v.y);
            As[c4 * 4 + 2][r] = f2tf32(v.z);
            As[c4 * 4 + 3][r] = f2tf32(v.w);
        }
        // Load B tile (16x128) into Bs[k][n]
#pragma unroll
        for (int i = 0; i < 2; i++) {
            int lin = tid + i * 256;
            int r = lin >> 5, c4 = lin & 31;
            float4 v = *(const float4*)(B + (size_t)(k0 + r) * 1024 + n0 + c4 * 4);
            Bs[r][c4 * 4 + 0] = f2tf32(v.x);
            Bs[r][c4 * 4 + 1] = f2tf32(v.y);
            Bs[r][c4 * 4 + 2] = f2tf32(v.z);
            Bs[r][c4 * 4 + 3] = f2tf32(v.w);
        }
        __syncthreads();

#pragma unroll
        for (int ks = 0; ks < BK; ks += 8) {
            uint32_t a[2][4];
#pragma unroll
            for (int mt = 0; mt < 2; mt++) {
                int r = wm * 32 + mt * 16 + (lane >> 2);
                a[mt][0] = As[ks + (lane & 3)][r];
                a[mt][1] = As[ks + (lane & 3)][r + 8];
                a[mt][2] = As[ks + (lane & 3) + 4][r];
                a[mt][3] = As[ks + (lane & 3) + 4][r + 8];
            }
#pragma unroll
            for (int nt = 0; nt < 8; nt++) {
                int cc = wn * 64 + nt * 8 + (lane >> 2);
                uint32_t b0 = Bs[ks + (lane & 3)][cc];
                uint32_t b1 = Bs[ks + (lane & 3) + 4][cc];
                mma_tf32(c[0][nt], a[0], b0, b1);
                mma_tf32(c[1][nt], a[1], b0, b1);
            }
        }
        __syncthreads();
    }

    // Epilogue
#pragma unroll
    for (int mt = 0; mt < 2; mt++) {
        int row = m0 + wm * 32 + mt * 16 + (lane >> 2);
#pragma unroll
        for (int nt = 0; nt < 8; nt++) {
            int col = n0 + wn * 64 + nt * 8 + 2 * (lane & 3);
#pragma unroll
            for (int half = 0; half < 2; half++) {
                int r = row + half * 8;
                float v0 = c[mt][nt][half * 2 + 0] * scale;
                float v1 = c[mt][nt][half * 2 + 1] * scale;
                if (csel <= 2) {
                    int nn = r >> 11, t = r & 2047;
                    int h = col >> 6, s = col & 63;
                    size_t idx = (((size_t)(nn * HH + h) * TT) + t) * SS + s;
                    *(float2*)&C[idx] = make_float2(v0, v1);
                } else {
                    *(float2*)&C[(size_t)r * 1024 + col] = make_float2(v0, v1);
                }
            }
        }
    }
}

// ============================================================================
// Flash attention: block = (q-tile of 128, h, n). 8 warps x 16 q-rows each.
// Online softmax, K/V staged in smem as tf32, P via smem for PV mma.
// ============================================================================
__global__ void __launch_bounds__(256) flash_kernel(const float* __restrict__ mask)
{
    extern __shared__ uint32_t sh[];
    uint32_t* Ksm = sh;                 // [64][68]
    uint32_t* Vsm = sh + 64 * 68;       // [64][68]
    uint32_t* Psm = sh + 2 * 64 * 68;   // [128][68]  (also Q staging, as float)
    float* QsmF = (float*)Psm;

    const int tid = threadIdx.x;
    const int lane = tid & 31, warp = tid >> 5;
    const int qt = blockIdx.x, h = blockIdx.y, n = blockIdx.z;
    const int q0 = qt * 128;
    const size_t headbase = ((size_t)(n * HH + h)) * TT * SS;

    // Stage Q tile 128x64 -> smem (plain f32)
#pragma unroll
    for (int i = 0; i < 8; i++) {
        int lin = tid + i * 256;
        int r = lin >> 4, c4 = lin & 15;
        float4 v = *(const float4*)(&g_Q[headbase + (size_t)(q0 + r) * SS + c4 * 4]);
        QsmF[r * 68 + c4 * 4 + 0] = v.x;
        QsmF[r * 68 + c4 * 4 + 1] = v.y;
        QsmF[r * 68 + c4 * 4 + 2] = v.z;
        QsmF[r * 68 + c4 * 4 + 3] = v.w;
    }
    __syncthreads();

    // Q A-fragments (held in registers for the whole kernel)
    uint32_t qa[8][4];
    {
        int r0 = warp * 16 + (lane >> 2);
#pragma unroll
        for (int ks = 0; ks < 8; ks++) {
            int col = ks * 8 + (lane & 3);
            qa[ks][0] = f2tf32(QsmF[r0 * 68 + col]);
            qa[ks][1] = f2tf32(QsmF[(r0 + 8) * 68 + col]);
            qa[ks][2] = f2tf32(QsmF[r0 * 68 + col + 4]);
            qa[ks][3] = f2tf32(QsmF[(r0 + 8) * 68 + col + 4]);
        }
    }
    __syncthreads();  // Psm region reused below

    float o[8][4];
#pragma unroll
    for (int nt = 0; nt < 8; nt++)
#pragma unroll
        for (int i = 0; i < 4; i++) o[nt][i] = 0.f;
    float mr0 = -INFINITY, mr1 = -INFINITY;
    float lr0 = 0.f, lr1 = 0.f;

    const float* mbase =
        mask + (((size_t)(n * HH + h)) * TT + q0 + warp * 16 + (lane >> 2)) * TT;

    const int r0 = warp * 16 + (lane >> 2);

    for (int j = 0; j < 32; j++) {
        const int k0 = j * 64;
        // Stage K,V tiles 64x64 -> smem (tf32)
#pragma unroll
        for (int i = 0; i < 4; i++) {
            int lin = tid + i * 256;
            int r = lin >> 4, c4 = lin & 15;
            float4 kv = *(const float4*)(&g_K[headbase + (size_t)(k0 + r) * SS + c4 * 4]);
            Ksm[r * 68 + c4 * 4 + 0] = f2tf32(kv.x);
            Ksm[r * 68 + c4 * 4 + 1] = f2tf32(kv.y);
            Ksm[r * 68 + c4 * 4 + 2] = f2tf32(kv.z);
            Ksm[r * 68 + c4 * 4 + 3] = f2tf32(kv.w);
            float4 vv = *(const float4*)(&g_V[headbase + (size_t)(k0 + r) * SS + c4 * 4]);
            Vsm[r * 68 + c4 * 4 + 0] = f2tf32(vv.x);
            Vsm[r * 68 + c4 * 4 + 1] = f2tf32(vv.y);
            Vsm[r * 68 + c4 * 4 + 2] = f2tf32(vv.z);
            Vsm[r * 68 + c4 * 4 + 3] = f2tf32(vv.w);
        }
        __syncthreads();

        // Scores = Q * K^T  (16 q-rows x 64 keys per warp)
        float sc[8][4];
#pragma unroll
        for (int nt = 0; nt < 8; nt++) {
            sc[nt][0] = sc[nt][1] = sc[nt][2] = sc[nt][3] = 0.f;
            int krow = nt * 8 + (lane >> 2);
#pragma unroll
            for (int ks = 0; ks < 8; ks++) {
                uint32_t b0 = Ksm[krow * 68 + ks * 8 + (lane & 3)];
                uint32_t b1 = Ksm[krow * 68 + ks * 8 + (lane & 3) + 4];
                mma_tf32(sc[nt], qa[ks], b0, b1);
            }
        }

        // Apply mask (direct global loads into fragment positions)
#pragma unroll
        for (int nt = 0; nt < 8; nt++) {
            int col = k0 + nt * 8 + 2 * (lane & 3);
            float2 m0v = *(const float2*)(mbase + col);
            float2 m1v = *(const float2*)(mbase + (size_t)8 * TT + col);
            sc[nt][0] += m0v.x * NEG_INF;
            sc[nt][1] += m0v.y * NEG_INF;
            sc[nt][2] += m1v.x * NEG_INF;
            sc[nt][3] += m1v.y * NEG_INF;
        }

        // Online softmax: row max over this tile
        float t0 = -INFINITY, t1 = -INFINITY;
#pragma unroll
        for (int nt = 0; nt < 8; nt++) {
            t0 = fmaxf(t0, fmaxf(sc[nt][0], sc[nt][1]));
            t1 = fmaxf(t1, fmaxf(sc[nt][2], sc[nt][3]));
        }
        t0 = fmaxf(t0, __shfl_xor_sync(0xffffffffu, t0, 1));
        t0 = fmaxf(t0, __shfl_xor_sync(0xffffffffu, t0, 2));
        t1 = fmaxf(t1, __shfl_xor_sync(0xffffffffu, t1, 1));
        t1 = fmaxf(t1, __shfl_xor_sync(0xffffffffu, t1, 2));

        float nm0 = fmaxf(mr0, t0), nm1 = fmaxf(mr1, t1);
        float cor0 = __expf(mr0 - nm0), cor1 = __expf(mr1 - nm1);
        mr0 = nm0; mr1 = nm1;

        float s0 = 0.f, s1 = 0.f;
#pragma unroll
        for (int nt = 0; nt < 8; nt++) {
            sc[nt][0] = __expf(sc[nt][0] - nm0);
            sc[nt][1] = __expf(sc[nt][1] - nm0);
            sc[nt][2] = __expf(sc[nt][2] - nm1);
            sc[nt][3] = __expf(sc[nt][3] - nm1);
            s0 += sc[nt][0] + sc[nt][1];
            s1 += sc[nt][2] + sc[nt][3];
        }
        s0 += __shfl_xor_sync(0xffffffffu, s0, 1);
        s0 += __shfl_xor_sync(0xffffffffu, s0, 2);
        s1 += __shfl_xor_sync(0xffffffffu, s1, 1);
        s1 += __shfl_xor_sync(0xffffffffu, s1, 2);
        lr0 = lr0 * cor0 + s0;
        lr1 = lr1 * cor1 + s1;

        // Rescale accumulator
#pragma unroll
        for (int nt = 0; nt < 8; nt++) {
            o[nt][0] *= cor0; o[nt][1] *= cor0;
            o[nt][2] *= cor1; o[nt][3] *= cor1;
        }

        // P -> smem (tf32), per-warp private region
#pragma unroll
        for (int nt = 0; nt < 8; nt++) {
            int col = nt * 8 + 2 * (lane & 3);
            Psm[r0 * 68 + col]           = f2tf32(sc[nt][0]);
            Psm[r0 * 68 + col + 1]       = f2tf32(sc[nt][1]);
            Psm[(r0 + 8) * 68 + col]     = f2tf32(sc[nt][2]);
            Psm[(r0 + 8) * 68 + col + 1] = f2tf32(sc[nt][3]);
        }
        __syncwarp();

        // P A-fragments
        uint32_t pa[8][4];
#pragma unroll
        for (int ks = 0; ks < 8; ks++) {
            int col = ks * 8 + (lane & 3);
            pa[ks][0] = Psm[r0 * 68 + col];
            pa[ks][1] = Psm[(r0 + 8) * 68 + col];
            pa[ks][2] = Psm[r0 * 68 + col + 4];
            pa[ks][3] = Psm[(r0 + 8) * 68 + col + 4];
        }

        // O += P * V
#pragma unroll
        for (int nt = 0; nt < 8; nt++) {
#pragma unroll
            for (int ks = 0; ks < 8; ks++) {
                int vrow = ks * 8 + (lane & 3);
                uint32_t b0 = Vsm[vrow * 68 + nt * 8 + (lane >> 2)];
                uint32_t b1 = Vsm[(vrow + 4) * 68 + nt * 8 + (lane >> 2)];
                mma_tf32(o[nt], pa[ks], b0, b1);
            }
        }
        __syncthreads();  // protect Ksm/Vsm before next tile load
    }

    // Normalize and write to g_O[n][q][h*64+s]
    float i0 = 1.f / lr0, i1 = 1.f / lr1;
    int r = q0 + warp * 16 + (lane >> 2);
    size_t ob0 = ((size_t)n * TT + r) * DD + h * SS;
    size_t ob1 = ((size_t)n * TT + r + 8) * DD + h * SS;
#pragma unroll
    for (int nt = 0; nt < 8; nt++) {
        int col = nt * 8 + 2 * (lane & 3);
        *(float2*)&g_O[ob0 + col] = make_float2(o[nt][0] * i0, o[nt][1] * i0);
        *(float2*)&g_O[ob1 + col] = make_float2(o[nt][2] * i1, o[nt][3] * i1);
    }
}

// ============================================================================
// Launch
// ============================================================================
extern "C" void kernel_launch(void* const* d_in, const int* in_sizes, int n_in,
                              void* d_out, int out_size)
{
    const float* qseq = (const float*)d_in[0];
    const float* rseq = (const float*)d_in[1];
    const float* mask = (const float*)d_in[2];
    const float* Wq   = (const float*)d_in[3];
    const float* Wk   = (const float*)d_in[4];
    const float* Wv   = (const float*)d_in[5];
    const float* Wo   = (const float*)d_in[6];
    float* out = (float*)d_out;

    dim3 gg(8, 32);  // N=1024/128, M=4096/128
    // Q/K/V projections (scale S^-0.5 fused into Q)
    gemm_tf32_kernel<<<gg, 256>>>(qseq, Wq, nullptr, 0, 0, 0.125f);
    gemm_tf32_kernel<<<gg, 256>>>(rseq, Wk, nullptr, 0, 1, 1.0f);
    gemm_tf32_kernel<<<gg, 256>>>(rseq, Wv, nullptr, 0, 2, 1.0f);

    // Flash attention
    const int smem_bytes = (2 * 64 * 68 + 128 * 68) * 4;  // 69632
    cudaFuncSetAttribute(flash_kernel, cudaFuncAttributeMaxDynamicSharedMemorySize,
                         smem_bytes);
    flash_kernel<<<dim3(16, HH, NB), 256, smem_bytes>>>(mask);

    // Output projection -> d_out
    gemm_tf32_kernel<<<gg, 256>>>(nullptr, Wo, out, 1, 3, 1.0f);
}

// round 3
// speedup vs baseline: 1.7057x; 1.7057x over previous
#include <cuda_runtime.h>
#include <cuda_bf16.h>
#include <cstdint>

// Problem constants
#define NB 2
#define HH 16
#define TT 2048
#define DD 1024
#define SS 64
#define NEG_INF (-1e9f)

// Scratch (device globals -> allowed; no runtime allocation)
// g_Q/g_K/g_V hold tf32-PRE-ROUNDED bit patterns (rounded in GEMM epilogue).
__device__ float g_Q[NB * HH * TT * SS];   // [n][h][t][s]
__device__ float g_K[NB * HH * TT * SS];   // [n][h][t][s]
__device__ float g_V[NB * HH * TT * SS];   // [n][h][t][s]
__device__ float g_O[NB * TT * DD];        // [n][t][h*64+s]  (full f32)

__device__ __forceinline__ uint32_t f2tf32(float x) {
    uint32_t r;
    asm("cvt.rna.tf32.f32 %0, %1;" : "=r"(r) : "f"(x));
    return r;
}

__device__ __forceinline__ void mma_tf32(float* c, const uint32_t* a, uint32_t b0, uint32_t b1) {
    asm volatile(
        "mma.sync.aligned.m16n8k8.row.col.f32.tf32.tf32.f32 "
        "{%0,%1,%2,%3}, {%4,%5,%6,%7}, {%8,%9}, {%0,%1,%2,%3};\n"
        : "+f"(c[0]), "+f"(c[1]), "+f"(c[2]), "+f"(c[3])
        : "r"(a[0]), "r"(a[1]), "r"(a[2]), "r"(a[3]), "r"(b0), "r"(b1));
}

__device__ __forceinline__ void cp16(void* smem_dst, const void* gsrc) {
    uint32_t d = (uint32_t)__cvta_generic_to_shared(smem_dst);
    asm volatile("cp.async.cg.shared.global [%0], [%1], 16;\n" :: "r"(d), "l"(gsrc));
}
__device__ __forceinline__ void cp_commit() { asm volatile("cp.async.commit_group;\n"); }
__device__ __forceinline__ void cp_wait0()  { asm volatile("cp.async.wait_group 0;\n"); }

// ============================================================================
// TF32 GEMM v2: C[M,1024] = A[M,1024] * B[1024,1024], row-major.
// BK=32, cp.async double-buffered. Converts to tf32 at fragment read.
// csel 0/1/2 -> scatter tf32-ROUNDED into g_Q/g_K/g_V head-major (with scale)
// csel 3     -> plain f32 row-major into Cext.   asel 1 -> A = g_O.
// ============================================================================
__global__ void __launch_bounds__(256, 2) gemm_tf32_kernel(
    const float* __restrict__ Aext, const float* __restrict__ B,
    float* __restrict__ Cext, int asel, int csel, float scale)
{
    constexpr int AP = 36;    // A smem pitch (floats): conflict-free frag reads
    constexpr int BP = 136;   // B smem pitch
    extern __shared__ float sm[];
    float* As = sm;                 // [2][128*AP]
    float* Bs = sm + 2 * 128 * AP;  // [2][32*BP]

    const float* A = asel ? g_O : Aext;
    float* C = (csel == 0) ? g_Q : (csel == 1) ? g_K : (csel == 2) ? g_V : Cext;

    const int tid = threadIdx.x;
    const int lane = tid & 31, warp = tid >> 5;
    const int wm = warp & 3, wn = warp >> 2;  // 4 x 2 warp grid
    const int m0 = blockIdx.y * 128, n0 = blockIdx.x * 128;

    float c[2][8][4];
#pragma unroll
    for (int mt = 0; mt < 2; mt++)
#pragma unroll
        for (int nt = 0; nt < 8; nt++)
#pragma unroll
            for (int i = 0; i < 4; i++) c[mt][nt][i] = 0.f;

    // prefetch: A tile 128x32 (4 f4/thread), B tile 32x128 (4 f4/thread)
    auto prefetch = [&](int k0, int stg) {
        float* Ad = As + stg * 128 * AP;
        float* Bd = Bs + stg * 32 * BP;
#pragma unroll
        for (int i = 0; i < 4; i++) {
            int lin = tid + i * 256;
            int r = lin >> 3, c16 = lin & 7;
            cp16(Ad + r * AP + c16 * 4, A + (size_t)(m0 + r) * 1024 + k0 + c16 * 4);
        }
#pragma unroll
        for (int i = 0; i < 4; i++) {
            int lin = tid + i * 256;
            int r = lin >> 5, c16 = lin & 31;
            cp16(Bd + r * BP + c16 * 4, B + (size_t)(k0 + r) * 1024 + n0 + c16 * 4);
        }
        cp_commit();
    };

    prefetch(0, 0);
    cp_wait0();
    __syncthreads();

    for (int t = 0; t < 32; t++) {
        if (t + 1 < 32) prefetch((t + 1) * 32, (t + 1) & 1);
        const float* Ab = As + (t & 1) * 128 * AP;
        const float* Bb = Bs + (t & 1) * 32 * BP;
#pragma unroll
        for (int ks = 0; ks < 32; ks += 8) {
            uint32_t a[2][4];
#pragma unroll
            for (int mt = 0; mt < 2; mt++) {
                int r = wm * 32 + mt * 16 + (lane >> 2);
                a[mt][0] = f2tf32(Ab[r * AP + ks + (lane & 3)]);
                a[mt][1] = f2tf32(Ab[(r + 8) * AP + ks + (lane & 3)]);
                a[mt][2] = f2tf32(Ab[r * AP + ks + (lane & 3) + 4]);
                a[mt][3] = f2tf32(Ab[(r + 8) * AP + ks + (lane & 3) + 4]);
            }
#pragma unroll
            for (int nt = 0; nt < 8; nt++) {
                int cc = wn * 64 + nt * 8 + (lane >> 2);
                uint32_t b0 = f2tf32(Bb[(ks + (lane & 3)) * BP + cc]);
                uint32_t b1 = f2tf32(Bb[(ks + (lane & 3) + 4) * BP + cc]);
                mma_tf32(c[0][nt], a[0], b0, b1);
                mma_tf32(c[1][nt], a[1], b0, b1);
            }
        }
        if (t + 1 < 32) {
            cp_wait0();
            __syncthreads();
        }
    }

    // Epilogue
#pragma unroll
    for (int mt = 0; mt < 2; mt++) {
        int row = m0 + wm * 32 + mt * 16 + (lane >> 2);
#pragma unroll
        for (int nt = 0; nt < 8; nt++) {
            int col = n0 + wn * 64 + nt * 8 + 2 * (lane & 3);
#pragma unroll
            for (int half = 0; half < 2; half++) {
                int r = row + half * 8;
                float v0 = c[mt][nt][half * 2 + 0] * scale;
                float v1 = c[mt][nt][half * 2 + 1] * scale;
                if (csel <= 2) {
                    // pre-round to tf32 so flash consumes raw bits
                    v0 = __uint_as_float(f2tf32(v0));
                    v1 = __uint_as_float(f2tf32(v1));
                    int nn = r >> 11, t = r & 2047;
                    int h = col >> 6, s = col & 63;
                    size_t idx = (((size_t)(nn * HH + h) * TT) + t) * SS + s;
                    *(float2*)&C[idx] = make_float2(v0, v1);
                } else {
                    *(float2*)&C[(size_t)r * 1024 + col] = make_float2(v0, v1);
                }
            }
        }
    }
}

// ============================================================================
// Flash attention v2: block = (q-tile 128, h, n), 8 warps x 16 q-rows.
// cp.async double-buffered K/V (pre-rounded tf32 bits), 1 barrier per tile.
// Psm: K pitch 68 (conflict-free K-frag), V pitch 72 (conflict-free V-frag).
// ============================================================================
__global__ void __launch_bounds__(256, 2) flash_kernel(const float* __restrict__ mask)
{
    extern __shared__ float sh[];
    float* Kb = sh;                     // [2][64*68]
    float* Vb = sh + 2 * 64 * 68;       // [2][64*72]
    uint32_t* Psm = (uint32_t*)(sh + 2 * 64 * 68 + 2 * 64 * 72);  // [128*68]

    const int tid = threadIdx.x;
    const int lane = tid & 31, warp = tid >> 5;
    const int qt = blockIdx.x, h = blockIdx.y, n = blockIdx.z;
    const int q0 = qt * 128;
    const size_t headbase = ((size_t)(n * HH + h)) * TT * SS;

    auto prefetchKV = [&](int j, int stg) {
        const int k0 = j * 64;
        float* Kd = Kb + stg * 64 * 68;
        float* Vd = Vb + stg * 64 * 72;
#pragma unroll
        for (int i = 0; i < 4; i++) {
            int lin = tid + i * 256;
            int r = lin >> 4, c16 = lin & 15;
            cp16(Kd + r * 68 + c16 * 4, &g_K[headbase + (size_t)(k0 + r) * SS + c16 * 4]);
            cp16(Vd + r * 72 + c16 * 4, &g_V[headbase + (size_t)(k0 + r) * SS + c16 * 4]);
        }
        cp_commit();
    };

    // Kick off tile 0 loads + stage Q into Psm via cp.async
    prefetchKV(0, 0);
#pragma unroll
    for (int i = 0; i < 8; i++) {
        int lin = tid + i * 256;
        int r = lin >> 4, c16 = lin & 15;
        cp16(Psm + r * 68 + c16 * 4, &g_Q[headbase + (size_t)(q0 + r) * SS + c16 * 4]);
    }
    cp_commit();
    cp_wait0();
    __syncthreads();

    const int r0 = warp * 16 + (lane >> 2);

    // Q A-fragments (pre-rounded tf32 bits — no convert)
    uint32_t qa[8][4];
#pragma unroll
    for (int ks = 0; ks < 8; ks++) {
        int col = ks * 8 + (lane & 3);
        qa[ks][0] = Psm[r0 * 68 + col];
        qa[ks][1] = Psm[(r0 + 8) * 68 + col];
        qa[ks][2] = Psm[r0 * 68 + col + 4];
        qa[ks][3] = Psm[(r0 + 8) * 68 + col + 4];
    }
    // Psm rows [warp*16, warp*16+16) are exclusively this warp's from here on.

    float o[8][4];
#pragma unroll
    for (int nt = 0; nt < 8; nt++)
#pragma unroll
        for (int i = 0; i < 4; i++) o[nt][i] = 0.f;
    float mr0 = -INFINITY, mr1 = -INFINITY;
    float lr0 = 0.f, lr1 = 0.f;

    const float* mbase =
        mask + (((size_t)(n * HH + h)) * TT + q0 + warp * 16 + (lane >> 2)) * TT;

    for (int j = 0; j < 32; j++) {
        if (j + 1 < 32) prefetchKV(j + 1, (j + 1) & 1);

        const uint32_t* Kc = (const uint32_t*)(Kb + (j & 1) * 64 * 68);
        const uint32_t* Vc = (const uint32_t*)(Vb + (j & 1) * 64 * 72);
        const int k0 = j * 64;

        // Scores = Q * K^T (16 q-rows x 64 keys per warp)
        float sc[8][4];
#pragma unroll
        for (int nt = 0; nt < 8; nt++) {
            sc[nt][0] = sc[nt][1] = sc[nt][2] = sc[nt][3] = 0.f;
            int krow = nt * 8 + (lane >> 2);
#pragma unroll
            for (int ks = 0; ks < 8; ks++) {
                uint32_t b0 = Kc[krow * 68 + ks * 8 + (lane & 3)];
                uint32_t b1 = Kc[krow * 68 + ks * 8 + (lane & 3) + 4];
                mma_tf32(sc[nt], qa[ks], b0, b1);
            }
        }

        // Apply mask (global loads; MLP across the unrolled loop)
#pragma unroll
        for (int nt = 0; nt < 8; nt++) {
            int col = k0 + nt * 8 + 2 * (lane & 3);
            float2 m0v = *(const float2*)(mbase + col);
            float2 m1v = *(const float2*)(mbase + (size_t)8 * TT + col);
            sc[nt][0] += m0v.x * NEG_INF;
            sc[nt][1] += m0v.y * NEG_INF;
            sc[nt][2] += m1v.x * NEG_INF;
            sc[nt][3] += m1v.y * NEG_INF;
        }

        // Online softmax
        float t0 = -INFINITY, t1 = -INFINITY;
#pragma unroll
        for (int nt = 0; nt < 8; nt++) {
            t0 = fmaxf(t0, fmaxf(sc[nt][0], sc[nt][1]));
            t1 = fmaxf(t1, fmaxf(sc[nt][2], sc[nt][3]));
        }
        t0 = fmaxf(t0, __shfl_xor_sync(0xffffffffu, t0, 1));
        t0 = fmaxf(t0, __shfl_xor_sync(0xffffffffu, t0, 2));
        t1 = fmaxf(t1, __shfl_xor_sync(0xffffffffu, t1, 1));
        t1 = fmaxf(t1, __shfl_xor_sync(0xffffffffu, t1, 2));

        float nm0 = fmaxf(mr0, t0), nm1 = fmaxf(mr1, t1);
        float cor0 = __expf(mr0 - nm0), cor1 = __expf(mr1 - nm1);
        mr0 = nm0; mr1 = nm1;

        float s0 = 0.f, s1 = 0.f;
#pragma unroll
        for (int nt = 0; nt < 8; nt++) {
            sc[nt][0] = __expf(sc[nt][0] - nm0);
            sc[nt][1] = __expf(sc[nt][1] - nm0);
            sc[nt][2] = __expf(sc[nt][2] - nm1);
            sc[nt][3] = __expf(sc[nt][3] - nm1);
            s0 += sc[nt][0] + sc[nt][1];
            s1 += sc[nt][2] + sc[nt][3];
        }
        s0 += __shfl_xor_sync(0xffffffffu, s0, 1);
        s0 += __shfl_xor_sync(0xffffffffu, s0, 2);
        s1 += __shfl_xor_sync(0xffffffffu, s1, 1);
        s1 += __shfl_xor_sync(0xffffffffu, s1, 2);
        lr0 = lr0 * cor0 + s0;
        lr1 = lr1 * cor1 + s1;

#pragma unroll
        for (int nt = 0; nt < 8; nt++) {
            o[nt][0] *= cor0; o[nt][1] *= cor0;
            o[nt][2] *= cor1; o[nt][3] *= cor1;
        }

        // P -> Psm (tf32 bits), per-warp private rows
#pragma unroll
        for (int nt = 0; nt < 8; nt++) {
            int col = nt * 8 + 2 * (lane & 3);
            Psm[r0 * 68 + col]           = f2tf32(sc[nt][0]);
            Psm[r0 * 68 + col + 1]       = f2tf32(sc[nt][1]);
            Psm[(r0 + 8) * 68 + col]     = f2tf32(sc[nt][2]);
            Psm[(r0 + 8) * 68 + col + 1] = f2tf32(sc[nt][3]);
        }
        __syncwarp();

        uint32_t pa[8][4];
#pragma unroll
        for (int ks = 0; ks < 8; ks++) {
            int col = ks * 8 + (lane & 3);
            pa[ks][0] = Psm[r0 * 68 + col];
            pa[ks][1] = Psm[(r0 + 8) * 68 + col];
            pa[ks][2] = Psm[r0 * 68 + col + 4];
            pa[ks][3] = Psm[(r0 + 8) * 68 + col + 4];
        }

        // O += P * V
#pragma unroll
        for (int nt = 0; nt < 8; nt++) {
#pragma unroll
            for (int ks = 0; ks < 8; ks++) {
                int vrow = ks * 8 + (lane & 3);
                uint32_t b0 = Vc[vrow * 72 + nt * 8 + (lane >> 2)];
                uint32_t b1 = Vc[(vrow + 4) * 72 + nt * 8 + (lane >> 2)];
                mma_tf32(o[nt], pa[ks], b0, b1);
            }
        }

        if (j + 1 < 32) {
            cp_wait0();        // next tile's loads done (overlapped with compute)
            __syncthreads();   // all warps done with current buffers
        }
    }

    // Normalize and write g_O[n][q][h*64+s] (full f32)
    float i0 = 1.f / lr0, i1 = 1.f / lr1;
    int r = q0 + warp * 16 + (lane >> 2);
    size_t ob0 = ((size_t)n * TT + r) * DD + h * SS;
    size_t ob1 = ((size_t)n * TT + r + 8) * DD + h * SS;
#pragma unroll
    for (int nt = 0; nt < 8; nt++) {
        int col = nt * 8 + 2 * (lane & 3);
        *(float2*)&g_O[ob0 + col] = make_float2(o[nt][0] * i0, o[nt][1] * i0);
        *(float2*)&g_O[ob1 + col] = make_float2(o[nt][2] * i1, o[nt][3] * i1);
    }
}

// ============================================================================
// Launch
// ============================================================================
extern "C" void kernel_launch(void* const* d_in, const int* in_sizes, int n_in,
                              void* d_out, int out_size)
{
    const float* qseq = (const float*)d_in[0];
    const float* rseq = (const float*)d_in[1];
    const float* mask = (const float*)d_in[2];
    const float* Wq   = (const float*)d_in[3];
    const float* Wk   = (const float*)d_in[4];
    const float* Wv   = (const float*)d_in[5];
    const float* Wo   = (const float*)d_in[6];
    float* out = (float*)d_out;

    const int gemm_smem = (2 * 128 * 36 + 2 * 32 * 136) * 4;        // 71680
    const int flash_smem = (2 * 64 * 68 + 2 * 64 * 72 + 128 * 68) * 4;  // 106496
    cudaFuncSetAttribute(gemm_tf32_kernel, cudaFuncAttributeMaxDynamicSharedMemorySize,
                         gemm_smem);
    cudaFuncSetAttribute(flash_kernel, cudaFuncAttributeMaxDynamicSharedMemorySize,
                         flash_smem);

    dim3 gg(8, 32);  // N=1024/128, M=4096/128
    gemm_tf32_kernel<<<gg, 256, gemm_smem>>>(qseq, Wq, nullptr, 0, 0, 0.125f);
    gemm_tf32_kernel<<<gg, 256, gemm_smem>>>(rseq, Wk, nullptr, 0, 1, 1.0f);
    gemm_tf32_kernel<<<gg, 256, gemm_smem>>>(rseq, Wv, nullptr, 0, 2, 1.0f);

    flash_kernel<<<dim3(16, HH, NB), 256, flash_smem>>>(mask);

    gemm_tf32_kernel<<<gg, 256, gemm_smem>>>(nullptr, Wo, out, 1, 3, 1.0f);
}

// round 5
// speedup vs baseline: 1.8494x; 1.0842x over previous
#include <cuda_runtime.h>
#include <cuda_bf16.h>
#include <cstdint>

// Problem constants
#define NB 2
#define HH 16
#define TT 2048
#define DD 1024
#define SS 64
#define NEG_INF (-1e9f)

// Scratch (device globals; no runtime allocation)
// All hold tf32-PRE-ROUNDED bit patterns except where noted.
__device__ float g_Q[NB * HH * TT * SS];   // [n][h][t][s]
__device__ float g_K[NB * HH * TT * SS];
__device__ float g_V[NB * HH * TT * SS];
__device__ float g_O[NB * TT * DD];        // [n][t][h*64+s]  (rounded by flash)
__device__ float g_Aq[NB * TT * DD];       // rounded qseq  [m][k]
__device__ float g_Ar[NB * TT * DD];       // rounded rseq  [m][k]
__device__ float g_Wr[4 * DD * DD];        // rounded weights, native [k][n]: Wq,Wk,Wv,Wo

__device__ __forceinline__ uint32_t f2tf32(float x) {
    uint32_t r;
    asm("cvt.rna.tf32.f32 %0, %1;" : "=r"(r) : "f"(x));
    return r;
}

__device__ __forceinline__ void mma_tf32(float* c, const uint32_t* a, uint32_t b0, uint32_t b1) {
    asm volatile(
        "mma.sync.aligned.m16n8k8.row.col.f32.tf32.tf32.f32 "
        "{%0,%1,%2,%3}, {%4,%5,%6,%7}, {%8,%9}, {%0,%1,%2,%3};\n"
        : "+f"(c[0]), "+f"(c[1]), "+f"(c[2]), "+f"(c[3])
        : "r"(a[0]), "r"(a[1]), "r"(a[2]), "r"(a[3]), "r"(b0), "r"(b1));
}

__device__ __forceinline__ void cp16(void* smem_dst, const void* gsrc) {
    uint32_t d = (uint32_t)__cvta_generic_to_shared(smem_dst);
    asm volatile("cp.async.cg.shared.global [%0], [%1], 16;\n" :: "r"(d), "l"(gsrc));
}
__device__ __forceinline__ void cp_commit() { asm volatile("cp.async.commit_group;\n"); }
__device__ __forceinline__ void cp_wait0()  { asm volatile("cp.async.wait_group 0;\n"); }
__device__ __forceinline__ void cp_wait1()  { asm volatile("cp.async.wait_group 1;\n"); }

// ============================================================================
// Prep: round activations to tf32 bits (elementwise copy)
// ============================================================================
__global__ void __launch_bounds__(256) prep_round_act(const float* __restrict__ q,
                                                      const float* __restrict__ r) {
    const float* src = blockIdx.z ? r : q;
    float* dst = blockIdx.z ? g_Ar : g_Aq;
    size_t i = ((size_t)blockIdx.x * 256 + threadIdx.x) * 4;
    float4 v = *(const float4*)(src + i);
    uint4 o;
    o.x = f2tf32(v.x); o.y = f2tf32(v.y); o.z = f2tf32(v.z); o.w = f2tf32(v.w);
    *(uint4*)(dst + i) = o;
}

// Prep: round weights to tf32 bits, native [k][n] layout preserved
__global__ void __launch_bounds__(256) prep_round_w(
    const float* __restrict__ W0, const float* __restrict__ W1,
    const float* __restrict__ W2, const float* __restrict__ W3) {
    const int z = blockIdx.z;
    const float* W = (z == 0) ? W0 : (z == 1) ? W1 : (z == 2) ? W2 : W3;
    float* dst = g_Wr + (size_t)z * DD * DD;
    size_t i = ((size_t)blockIdx.x * 256 + threadIdx.x) * 4;
    float4 v = *(const float4*)(W + i);
    uint4 o;
    o.x = f2tf32(v.x); o.y = f2tf32(v.y); o.z = f2tf32(v.z); o.w = f2tf32(v.w);
    *(uint4*)(dst + i) = o;
}

// ============================================================================
// TF32 GEMM v3: C[M,1024] = A[M,1024] * B[1024,1024]; inputs pre-rounded bits.
// BK=32, cp.async double-buffered, zero cvt in the mainloop.
// mode 0: z=blockIdx.z in {0,1,2} -> A = g_Aq/g_Ar, B = g_Wr[z], scatter rounded
// mode 1: A = g_O, B = g_Wr[3] -> plain f32 row-major into outp
// ============================================================================
__global__ void __launch_bounds__(256, 2) gemm_tf32_kernel(
    float* __restrict__ outp, int mode)
{
    constexpr int AP = 36;    // A smem pitch (u32): conflict-free frag reads
    constexpr int BP = 136;   // B smem pitch
    extern __shared__ uint32_t sm[];
    uint32_t* As = sm;                 // [2][128*AP]
    uint32_t* Bs = sm + 2 * 128 * AP;  // [2][32*BP]

    const int z = blockIdx.z;
    const float* A = (mode == 1) ? g_O : (z == 0 ? g_Aq : g_Ar);
    const float* B = g_Wr + (size_t)((mode == 1) ? 3 : z) * DD * DD;

    const int tid = threadIdx.x;
    const int lane = tid & 31, warp = tid >> 5;
    const int wm = warp & 3, wn = warp >> 2;  // 4 x 2 warp grid
    const int m0 = blockIdx.y * 128, n0 = blockIdx.x * 128;

    float c[2][8][4];
#pragma unroll
    for (int mt = 0; mt < 2; mt++)
#pragma unroll
        for (int nt = 0; nt < 8; nt++)
#pragma unroll
            for (int i = 0; i < 4; i++) c[mt][nt][i] = 0.f;

    auto prefetch = [&](int k0, int stg) {
        uint32_t* Ad = As + stg * 128 * AP;
        uint32_t* Bd = Bs + stg * 32 * BP;
#pragma unroll
        for (int i = 0; i < 4; i++) {
            int lin = tid + i * 256;
            int r = lin >> 3, c16 = lin & 7;
            cp16(Ad + r * AP + c16 * 4, A + (size_t)(m0 + r) * 1024 + k0 + c16 * 4);
        }
#pragma unroll
        for (int i = 0; i < 4; i++) {
            int lin = tid + i * 256;
            int r = lin >> 5, c16 = lin & 31;
            cp16(Bd + r * BP + c16 * 4, B + (size_t)(k0 + r) * 1024 + n0 + c16 * 4);
        }
        cp_commit();
    };

    prefetch(0, 0);
    cp_wait0();
    __syncthreads();

    for (int t = 0; t < 32; t++) {
        if (t + 1 < 32) prefetch((t + 1) * 32, (t + 1) & 1);
        const uint32_t* Ab = As + (t & 1) * 128 * AP;
        const uint32_t* Bb = Bs + (t & 1) * 32 * BP;
#pragma unroll
        for (int ks = 0; ks < 32; ks += 8) {
            uint32_t a[2][4];
#pragma unroll
            for (int mt = 0; mt < 2; mt++) {
                int r = wm * 32 + mt * 16 + (lane >> 2);
                a[mt][0] = Ab[r * AP + ks + (lane & 3)];
                a[mt][1] = Ab[(r + 8) * AP + ks + (lane & 3)];
                a[mt][2] = Ab[r * AP + ks + (lane & 3) + 4];
                a[mt][3] = Ab[(r + 8) * AP + ks + (lane & 3) + 4];
            }
#pragma unroll
            for (int nt = 0; nt < 8; nt++) {
                int cc = wn * 64 + nt * 8 + (lane >> 2);
                uint32_t b0 = Bb[(ks + (lane & 3)) * BP + cc];
                uint32_t b1 = Bb[(ks + (lane & 3) + 4) * BP + cc];
                mma_tf32(c[0][nt], a[0], b0, b1);
                mma_tf32(c[1][nt], a[1], b0, b1);
            }
        }
        if (t + 1 < 32) {
            cp_wait0();
            __syncthreads();
        }
    }

    // Epilogue
    const float scale = (mode == 0 && z == 0) ? 0.125f : 1.0f;
#pragma unroll
    for (int mt = 0; mt < 2; mt++) {
        int row = m0 + wm * 32 + mt * 16 + (lane >> 2);
#pragma unroll
        for (int nt = 0; nt < 8; nt++) {
            int col = n0 + wn * 64 + nt * 8 + 2 * (lane & 3);
#pragma unroll
            for (int half = 0; half < 2; half++) {
                int r = row + half * 8;
                float v0 = c[mt][nt][half * 2 + 0] * scale;
                float v1 = c[mt][nt][half * 2 + 1] * scale;
                if (mode == 0) {
                    v0 = __uint_as_float(f2tf32(v0));
                    v1 = __uint_as_float(f2tf32(v1));
                    int nn = r >> 11, t = r & 2047;
                    int h = col >> 6, s = col & 63;
                    size_t idx = (((size_t)(nn * HH + h) * TT) + t) * SS + s;
                    float* dstb = (z == 0) ? g_Q : (z == 1) ? g_K : g_V;
                    *(float2*)&dstb[idx] = make_float2(v0, v1);
                } else {
                    *(float2*)&outp[(size_t)r * 1024 + col] = make_float2(v0, v1);
                }
            }
        }
    }
}

// ============================================================================
// Flash attention v3: mask folded into mma accumulator init (loads issue
// before the HMMA chain -> latency hidden). Otherwise as R3.
// ============================================================================
__global__ void __launch_bounds__(256, 2) flash_kernel(const float* __restrict__ mask)
{
    extern __shared__ float sh[];
    float* Kb = sh;                     // [2][64*68]
    float* Vb = sh + 2 * 64 * 68;       // [2][64*72]
    uint32_t* Psm = (uint32_t*)(sh + 2 * 64 * 68 + 2 * 64 * 72);  // [128*68]

    const int tid = threadIdx.x;
    const int lane = tid & 31, warp = tid >> 5;
    const int qt = blockIdx.x, h = blockIdx.y, n = blockIdx.z;
    const int q0 = qt * 128;
    const size_t headbase = ((size_t)(n * HH + h)) * TT * SS;

    auto prefetchKV = [&](int j, int stg) {
        const int k0 = j * 64;
        float* Kd = Kb + stg * 64 * 68;
        float* Vd = Vb + stg * 64 * 72;
#pragma unroll
        for (int i = 0; i < 4; i++) {
            int lin = tid + i * 256;
            int r = lin >> 4, c16 = lin & 15;
            cp16(Kd + r * 68 + c16 * 4, &g_K[headbase + (size_t)(k0 + r) * SS + c16 * 4]);
            cp16(Vd + r * 72 + c16 * 4, &g_V[headbase + (size_t)(k0 + r) * SS + c16 * 4]);
        }
        cp_commit();
    };

    prefetchKV(0, 0);
#pragma unroll
    for (int i = 0; i < 8; i++) {
        int lin = tid + i * 256;
        int r = lin >> 4, c16 = lin & 15;
        cp16(Psm + r * 68 + c16 * 4, &g_Q[headbase + (size_t)(q0 + r) * SS + c16 * 4]);
    }
    cp_commit();
    cp_wait0();
    __syncthreads();

    const int r0 = warp * 16 + (lane >> 2);

    uint32_t qa[8][4];
#pragma unroll
    for (int ks = 0; ks < 8; ks++) {
        int col = ks * 8 + (lane & 3);
        qa[ks][0] = Psm[r0 * 68 + col];
        qa[ks][1] = Psm[(r0 + 8) * 68 + col];
        qa[ks][2] = Psm[r0 * 68 + col + 4];
        qa[ks][3] = Psm[(r0 + 8) * 68 + col + 4];
    }

    float o[8][4];
#pragma unroll
    for (int nt = 0; nt < 8; nt++)
#pragma unroll
        for (int i = 0; i < 4; i++) o[nt][i] = 0.f;
    float mr0 = -INFINITY, mr1 = -INFINITY;
    float lr0 = 0.f, lr1 = 0.f;

    const float* mbase =
        mask + (((size_t)(n * HH + h)) * TT + q0 + warp * 16 + (lane >> 2)) * TT;

    for (int j = 0; j < 32; j++) {
        if (j + 1 < 32) prefetchKV(j + 1, (j + 1) & 1);

        const uint32_t* Kc = (const uint32_t*)(Kb + (j & 1) * 64 * 68);
        const uint32_t* Vc = (const uint32_t*)(Vb + (j & 1) * 64 * 72);
        const int k0 = j * 64;

        // Init scores from the mask (loads issued BEFORE the mma chain)
        float sc[8][4];
#pragma unroll
        for (int nt = 0; nt < 8; nt++) {
            int col = k0 + nt * 8 + 2 * (lane & 3);
            float2 m0v = *(const float2*)(mbase + col);
            float2 m1v = *(const float2*)(mbase + (size_t)8 * TT + col);
            sc[nt][0] = m0v.x * NEG_INF;
            sc[nt][1] = m0v.y * NEG_INF;
            sc[nt][2] = m1v.x * NEG_INF;
            sc[nt][3] = m1v.y * NEG_INF;
        }

        // sc += Q * K^T
#pragma unroll
        for (int nt = 0; nt < 8; nt++) {
            int krow = nt * 8 + (lane >> 2);
#pragma unroll
            for (int ks = 0; ks < 8; ks++) {
                uint32_t b0 = Kc[krow * 68 + ks * 8 + (lane & 3)];
                uint32_t b1 = Kc[krow * 68 + ks * 8 + (lane & 3) + 4];
                mma_tf32(sc[nt], qa[ks], b0, b1);
            }
        }

        // Online softmax
        float t0 = -INFINITY, t1 = -INFINITY;
#pragma unroll
        for (int nt = 0; nt < 8; nt++) {
            t0 = fmaxf(t0, fmaxf(sc[nt][0], sc[nt][1]));
            t1 = fmaxf(t1, fmaxf(sc[nt][2], sc[nt][3]));
        }
        t0 = fmaxf(t0, __shfl_xor_sync(0xffffffffu, t0, 1));
        t0 = fmaxf(t0, __shfl_xor_sync(0xffffffffu, t0, 2));
        t1 = fmaxf(t1, __shfl_xor_sync(0xffffffffu, t1, 1));
        t1 = fmaxf(t1, __shfl_xor_sync(0xffffffffu, t1, 2));

        float nm0 = fmaxf(mr0, t0), nm1 = fmaxf(mr1, t1);
        float cor0 = __expf(mr0 - nm0), cor1 = __expf(mr1 - nm1);
        mr0 = nm0; mr1 = nm1;

        float s0 = 0.f, s1 = 0.f;
#pragma unroll
        for (int nt = 0; nt < 8; nt++) {
            sc[nt][0] = __expf(sc[nt][0] - nm0);
            sc[nt][1] = __expf(sc[nt][1] - nm0);
            sc[nt][2] = __expf(sc[nt][2] - nm1);
            sc[nt][3] = __expf(sc[nt][3] - nm1);
            s0 += sc[nt][0] + sc[nt][1];
            s1 += sc[nt][2] + sc[nt][3];
        }
        s0 += __shfl_xor_sync(0xffffffffu, s0, 1);
        s0 += __shfl_xor_sync(0xffffffffu, s0, 2);
        s1 += __shfl_xor_sync(0xffffffffu, s1, 1);
        s1 += __shfl_xor_sync(0xffffffffu, s1, 2);
        lr0 = lr0 * cor0 + s0;
        lr1 = lr1 * cor1 + s1;

#pragma unroll
        for (int nt = 0; nt < 8; nt++) {
            o[nt][0] *= cor0; o[nt][1] *= cor0;
            o[nt][2] *= cor1; o[nt][3] *= cor1;
        }

        // P -> Psm (tf32 bits), per-warp private rows
#pragma unroll
        for (int nt = 0; nt < 8; nt++) {
            int col = nt * 8 + 2 * (lane & 3);
            Psm[r0 * 68 + col]           = f2tf32(sc[nt][0]);
            Psm[r0 * 68 + col + 1]       = f2tf32(sc[nt][1]);
            Psm[(r0 + 8) * 68 + col]     = f2tf32(sc[nt][2]);
            Psm[(r0 + 8) * 68 + col + 1] = f2tf32(sc[nt][3]);
        }
        __syncwarp();

        uint32_t pa[8][4];
#pragma unroll
        for (int ks = 0; ks < 8; ks++) {
            int col = ks * 8 + (lane & 3);
            pa[ks][0] = Psm[r0 * 68 + col];
            pa[ks][1] = Psm[(r0 + 8) * 68 + col];
            pa[ks][2] = Psm[r0 * 68 + col + 4];
            pa[ks][3] = Psm[(r0 + 8) * 68 + col + 4];
        }

        // O += P * V
#pragma unroll
        for (int nt = 0; nt < 8; nt++) {
#pragma unroll
            for (int ks = 0; ks < 8; ks++) {
                int vrow = ks * 8 + (lane & 3);
                uint32_t b0 = Vc[vrow * 72 + nt * 8 + (lane >> 2)];
                uint32_t b1 = Vc[(vrow + 4) * 72 + nt * 8 + (lane >> 2)];
                mma_tf32(o[nt], pa[ks], b0, b1);
            }
        }

        if (j + 1 < 32) {
            cp_wait0();
            __syncthreads();
        }
    }

    // Normalize, round to tf32 bits (feeds out-proj GEMM), write g_O
    float i0 = 1.f / lr0, i1 = 1.f / lr1;
    int r = q0 + warp * 16 + (lane >> 2);
    size_t ob0 = ((size_t)n * TT + r) * DD + h * SS;
    size_t ob1 = ((size_t)n * TT + r + 8) * DD + h * SS;
#pragma unroll
    for (int nt = 0; nt < 8; nt++) {
        int col = nt * 8 + 2 * (lane & 3);
        *(float2*)&g_O[ob0 + col] = make_float2(
            __uint_as_float(f2tf32(o[nt][0] * i0)),
            __uint_as_float(f2tf32(o[nt][1] * i0)));
        *(float2*)&g_O[ob1 + col] = make_float2(
            __uint_as_float(f2tf32(o[nt][2] * i1)),
            __uint_as_float(f2tf32(o[nt][3] * i1)));
    }
}

// ============================================================================
// Launch
// ============================================================================
extern "C" void kernel_launch(void* const* d_in, const int* in_sizes, int n_in,
                              void* d_out, int out_size)
{
    const float* qseq = (const float*)d_in[0];
    const float* rseq = (const float*)d_in[1];
    const float* mask = (const float*)d_in[2];
    const float* Wq   = (const float*)d_in[3];
    const float* Wk   = (const float*)d_in[4];
    const float* Wv   = (const float*)d_in[5];
    const float* Wo   = (const float*)d_in[6];
    float* out = (float*)d_out;

    const int gemm_smem = (2 * 128 * 36 + 2 * 32 * 136) * 4;            // 71680
    const int flash_smem = (2 * 64 * 68 + 2 * 64 * 72 + 128 * 68) * 4;  // 106496
    cudaFuncSetAttribute(gemm_tf32_kernel, cudaFuncAttributeMaxDynamicSharedMemorySize,
                         gemm_smem);
    cudaFuncSetAttribute(flash_kernel, cudaFuncAttributeMaxDynamicSharedMemorySize,
                         flash_smem);

    // Prep: round activations + weights to tf32 bits
    prep_round_act<<<dim3(4096, 1, 2), 256>>>(qseq, rseq);
    prep_round_w<<<dim3(1024, 1, 4), 256>>>(Wq, Wk, Wv, Wo);

    // QKV projections fused into one launch over z
    gemm_tf32_kernel<<<dim3(8, 32, 3), 256, gemm_smem>>>(nullptr, 0);

    // Flash attention
    flash_kernel<<<dim3(16, HH, NB), 256, flash_smem>>>(mask);

    // Output projection -> d_out
    gemm_tf32_kernel<<<dim3(8, 32, 1), 256, gemm_smem>>>(out, 1);
}

// round 6
// speedup vs baseline: 1.9111x; 1.0334x over previous
#include <cuda_runtime.h>
#include <cuda_bf16.h>
#include <cstdint>

// Problem constants
#define NB 2
#define HH 16
#define TT 2048
#define DD 1024
#define SS 64
#define NEG_INF (-1e9f)

// Scratch (device globals; no runtime allocation)
// All hold tf32-PRE-ROUNDED bit patterns except where noted.
__device__ float g_Q[NB * HH * TT * SS];   // [n][h][t][s]
__device__ float g_K[NB * HH * TT * SS];
__device__ float g_V[NB * HH * TT * SS];
__device__ float g_O[NB * TT * DD];        // [n][t][h*64+s]  (rounded by flash)
__device__ float g_Aq[NB * TT * DD];       // rounded qseq  [m][k]
__device__ float g_Ar[NB * TT * DD];       // rounded rseq  [m][k]
__device__ float g_Wr[4 * DD * DD];        // rounded weights, native [k][n]: Wq,Wk,Wv,Wo

__device__ __forceinline__ uint32_t f2tf32(float x) {
    uint32_t r;
    asm("cvt.rna.tf32.f32 %0, %1;" : "=r"(r) : "f"(x));
    return r;
}

__device__ __forceinline__ void mma_tf32(float* c, const uint32_t* a, uint32_t b0, uint32_t b1) {
    asm volatile(
        "mma.sync.aligned.m16n8k8.row.col.f32.tf32.tf32.f32 "
        "{%0,%1,%2,%3}, {%4,%5,%6,%7}, {%8,%9}, {%0,%1,%2,%3};\n"
        : "+f"(c[0]), "+f"(c[1]), "+f"(c[2]), "+f"(c[3])
        : "r"(a[0]), "r"(a[1]), "r"(a[2]), "r"(a[3]), "r"(b0), "r"(b1));
}

__device__ __forceinline__ void cp16(void* smem_dst, const void* gsrc) {
    uint32_t d = (uint32_t)__cvta_generic_to_shared(smem_dst);
    asm volatile("cp.async.cg.shared.global [%0], [%1], 16;\n" :: "r"(d), "l"(gsrc));
}
__device__ __forceinline__ void cp_commit() { asm volatile("cp.async.commit_group;\n"); }
__device__ __forceinline__ void cp_wait0()  { asm volatile("cp.async.wait_group 0;\n"); }
__device__ __forceinline__ void cp_wait1()  { asm volatile("cp.async.wait_group 1;\n"); }
__device__ __forceinline__ void l2_prefetch(const void* p) {
    asm volatile("prefetch.global.L2 [%0];" :: "l"(p));
}

// ============================================================================
// Prep: round activations to tf32 bits (elementwise copy)
// ============================================================================
__global__ void __launch_bounds__(256) prep_round_act(const float* __restrict__ q,
                                                      const float* __restrict__ r) {
    const float* src = blockIdx.z ? r : q;
    float* dst = blockIdx.z ? g_Ar : g_Aq;
    size_t i = ((size_t)blockIdx.x * 256 + threadIdx.x) * 4;
    float4 v = *(const float4*)(src + i);
    uint4 o;
    o.x = f2tf32(v.x); o.y = f2tf32(v.y); o.z = f2tf32(v.z); o.w = f2tf32(v.w);
    *(uint4*)(dst + i) = o;
}

// Prep: round weights to tf32 bits, native [k][n] layout preserved
__global__ void __launch_bounds__(256) prep_round_w(
    const float* __restrict__ W0, const float* __restrict__ W1,
    const float* __restrict__ W2, const float* __restrict__ W3) {
    const int z = blockIdx.z;
    const float* W = (z == 0) ? W0 : (z == 1) ? W1 : (z == 2) ? W2 : W3;
    float* dst = g_Wr + (size_t)z * DD * DD;
    size_t i = ((size_t)blockIdx.x * 256 + threadIdx.x) * 4;
    float4 v = *(const float4*)(W + i);
    uint4 o;
    o.x = f2tf32(v.x); o.y = f2tf32(v.y); o.z = f2tf32(v.z); o.w = f2tf32(v.w);
    *(uint4*)(dst + i) = o;
}

// ============================================================================
// TF32 GEMM v4: 3-stage cp.async pipeline (~2 tiles of latency hiding).
// C[M,1024] = A[M,1024] * B[1024,1024]; inputs pre-rounded tf32 bits.
// mode 0: z=blockIdx.z in {0,1,2} -> A = g_Aq/g_Ar, B = g_Wr[z], scatter rounded
// mode 1: A = g_O, B = g_Wr[3] -> plain f32 row-major into outp
// ============================================================================
__global__ void __launch_bounds__(256, 2) gemm_tf32_kernel(
    float* __restrict__ outp, int mode)
{
    constexpr int AP = 36;    // A smem pitch (u32): conflict-free frag reads
    constexpr int BP = 136;   // B smem pitch
    constexpr int STG = 128 * AP + 32 * BP;   // 8960 u32 per stage
    extern __shared__ uint32_t sm[];          // 3 stages

    const int z = blockIdx.z;
    const float* A = (mode == 1) ? g_O : (z == 0 ? g_Aq : g_Ar);
    const float* B = g_Wr + (size_t)((mode == 1) ? 3 : z) * DD * DD;

    const int tid = threadIdx.x;
    const int lane = tid & 31, warp = tid >> 5;
    const int wm = warp & 3, wn = warp >> 2;  // 4 x 2 warp grid
    const int m0 = blockIdx.y * 128, n0 = blockIdx.x * 128;

    float c[2][8][4];
#pragma unroll
    for (int mt = 0; mt < 2; mt++)
#pragma unroll
        for (int nt = 0; nt < 8; nt++)
#pragma unroll
            for (int i = 0; i < 4; i++) c[mt][nt][i] = 0.f;

    auto prefetch = [&](int k0, int stg) {
        uint32_t* Ad = sm + stg * STG;
        uint32_t* Bd = Ad + 128 * AP;
#pragma unroll
        for (int i = 0; i < 4; i++) {
            int lin = tid + i * 256;
            int r = lin >> 3, c16 = lin & 7;
            cp16(Ad + r * AP + c16 * 4, A + (size_t)(m0 + r) * 1024 + k0 + c16 * 4);
        }
#pragma unroll
        for (int i = 0; i < 4; i++) {
            int lin = tid + i * 256;
            int r = lin >> 5, c16 = lin & 31;
            cp16(Bd + r * BP + c16 * 4, B + (size_t)(k0 + r) * 1024 + n0 + c16 * 4);
        }
        cp_commit();
    };

    prefetch(0, 0);
    prefetch(32, 1);

    for (int t = 0; t < 32; t++) {
        cp_wait1();          // stage t complete; stage t+1 may still fly
        __syncthreads();
        if (t + 2 < 32) prefetch((t + 2) * 32, (t + 2) % 3);
        else cp_commit();    // keep group arithmetic uniform

        const uint32_t* Ab = sm + (t % 3) * STG;
        const uint32_t* Bb = Ab + 128 * AP;
#pragma unroll
        for (int ks = 0; ks < 32; ks += 8) {
            uint32_t a[2][4];
#pragma unroll
            for (int mt = 0; mt < 2; mt++) {
                int r = wm * 32 + mt * 16 + (lane >> 2);
                a[mt][0] = Ab[r * AP + ks + (lane & 3)];
                a[mt][1] = Ab[(r + 8) * AP + ks + (lane & 3)];
                a[mt][2] = Ab[r * AP + ks + (lane & 3) + 4];
                a[mt][3] = Ab[(r + 8) * AP + ks + (lane & 3) + 4];
            }
#pragma unroll
            for (int nt = 0; nt < 8; nt++) {
                int cc = wn * 64 + nt * 8 + (lane >> 2);
                uint32_t b0 = Bb[(ks + (lane & 3)) * BP + cc];
                uint32_t b1 = Bb[(ks + (lane & 3) + 4) * BP + cc];
                mma_tf32(c[0][nt], a[0], b0, b1);
                mma_tf32(c[1][nt], a[1], b0, b1);
            }
        }
    }

    // Epilogue
    const float scale = (mode == 0 && z == 0) ? 0.125f : 1.0f;
#pragma unroll
    for (int mt = 0; mt < 2; mt++) {
        int row = m0 + wm * 32 + mt * 16 + (lane >> 2);
#pragma unroll
        for (int nt = 0; nt < 8; nt++) {
            int col = n0 + wn * 64 + nt * 8 + 2 * (lane & 3);
#pragma unroll
            for (int half = 0; half < 2; half++) {
                int r = row + half * 8;
                float v0 = c[mt][nt][half * 2 + 0] * scale;
                float v1 = c[mt][nt][half * 2 + 1] * scale;
                if (mode == 0) {
                    v0 = __uint_as_float(f2tf32(v0));
                    v1 = __uint_as_float(f2tf32(v1));
                    int nn = r >> 11, t = r & 2047;
                    int h = col >> 6, s = col & 63;
                    size_t idx = (((size_t)(nn * HH + h) * TT) + t) * SS + s;
                    float* dstb = (z == 0) ? g_Q : (z == 1) ? g_K : g_V;
                    *(float2*)&dstb[idx] = make_float2(v0, v1);
                } else {
                    *(float2*)&outp[(size_t)r * 1024 + col] = make_float2(v0, v1);
                }
            }
        }
    }
}

// ============================================================================
// Flash attention v4:
//  - mask LDGs issue BEFORE the KV wait/barrier (latency overlaps barrier+chain)
//  - L2 prefetch of next tile's mask during current tile (1 instr/warp/tile)
//  - P stored with STS.64
// ============================================================================
__global__ void __launch_bounds__(256, 2) flash_kernel(const float* __restrict__ mask)
{
    extern __shared__ float sh[];
    float* Kb = sh;                     // [2][64*68]
    float* Vb = sh + 2 * 64 * 68;       // [2][64*72]
    uint32_t* Psm = (uint32_t*)(sh + 2 * 64 * 68 + 2 * 64 * 72);  // [128*68]

    const int tid = threadIdx.x;
    const int lane = tid & 31, warp = tid >> 5;
    const int qt = blockIdx.x, h = blockIdx.y, n = blockIdx.z;
    const int q0 = qt * 128;
    const size_t headbase = ((size_t)(n * HH + h)) * TT * SS;

    auto prefetchKV = [&](int j, int stg) {
        const int k0 = j * 64;
        float* Kd = Kb + stg * 64 * 68;
        float* Vd = Vb + stg * 64 * 72;
#pragma unroll
        for (int i = 0; i < 4; i++) {
            int lin = tid + i * 256;
            int r = lin >> 4, c16 = lin & 15;
            cp16(Kd + r * 68 + c16 * 4, &g_K[headbase + (size_t)(k0 + r) * SS + c16 * 4]);
            cp16(Vd + r * 72 + c16 * 4, &g_V[headbase + (size_t)(k0 + r) * SS + c16 * 4]);
        }
        cp_commit();
    };

    // Per-warp mask base (row 0 of this warp's 16 rows)
    const float* mwarp =
        mask + (((size_t)(n * HH + h)) * TT + q0 + warp * 16) * TT;
    // Per-lane mask row base for fragment loads
    const float* mbase = mwarp + (size_t)(lane >> 2) * TT;

    prefetchKV(0, 0);
#pragma unroll
    for (int i = 0; i < 8; i++) {
        int lin = tid + i * 256;
        int r = lin >> 4, c16 = lin & 15;
        cp16(Psm + r * 68 + c16 * 4, &g_Q[headbase + (size_t)(q0 + r) * SS + c16 * 4]);
    }
    cp_commit();
    // L2 prefetch mask tile 0 (32 x 128B lines per warp: lane -> (row, half))
    l2_prefetch(mwarp + (size_t)(lane >> 1) * TT + (lane & 1) * 32);
    cp_wait0();
    __syncthreads();

    const int r0 = warp * 16 + (lane >> 2);

    uint32_t qa[8][4];
#pragma unroll
    for (int ks = 0; ks < 8; ks++) {
        int col = ks * 8 + (lane & 3);
        qa[ks][0] = Psm[r0 * 68 + col];
        qa[ks][1] = Psm[(r0 + 8) * 68 + col];
        qa[ks][2] = Psm[r0 * 68 + col + 4];
        qa[ks][3] = Psm[(r0 + 8) * 68 + col + 4];
    }

    float o[8][4];
#pragma unroll
    for (int nt = 0; nt < 8; nt++)
#pragma unroll
        for (int i = 0; i < 4; i++) o[nt][i] = 0.f;
    float mr0 = -INFINITY, mr1 = -INFINITY;
    float lr0 = 0.f, lr1 = 0.f;

    for (int j = 0; j < 32; j++) {
        const int k0 = j * 64;

        // 1. Init scores from mask — LDGs issue BEFORE the KV wait below,
        //    so their (L2-hit) latency overlaps the barrier + chain start.
        float sc[8][4];
#pragma unroll
        for (int nt = 0; nt < 8; nt++) {
            int col = k0 + nt * 8 + 2 * (lane & 3);
            float2 m0v = *(const float2*)(mbase + col);
            float2 m1v = *(const float2*)(mbase + (size_t)8 * TT + col);
            sc[nt][0] = m0v.x * NEG_INF;
            sc[nt][1] = m0v.y * NEG_INF;
            sc[nt][2] = m1v.x * NEG_INF;
            sc[nt][3] = m1v.y * NEG_INF;
        }

        // 2. KV(j) ready; all warps done with the other buffer
        cp_wait0();
        __syncthreads();

        // 3. Prefetch KV(j+1) + L2-prefetch mask(j+1)
        if (j + 1 < 32) {
            prefetchKV(j + 1, (j + 1) & 1);
            l2_prefetch(mwarp + (size_t)(lane >> 1) * TT + (j + 1) * 64 + (lane & 1) * 32);
        }

        const uint32_t* Kc = (const uint32_t*)(Kb + (j & 1) * 64 * 68);
        const uint32_t* Vc = (const uint32_t*)(Vb + (j & 1) * 64 * 72);

        // 4. sc += Q * K^T
#pragma unroll
        for (int nt = 0; nt < 8; nt++) {
            int krow = nt * 8 + (lane >> 2);
#pragma unroll
            for (int ks = 0; ks < 8; ks++) {
                uint32_t b0 = Kc[krow * 68 + ks * 8 + (lane & 3)];
                uint32_t b1 = Kc[krow * 68 + ks * 8 + (lane & 3) + 4];
                mma_tf32(sc[nt], qa[ks], b0, b1);
            }
        }

        // 5. Online softmax
        float t0 = -INFINITY, t1 = -INFINITY;
#pragma unroll
        for (int nt = 0; nt < 8; nt++) {
            t0 = fmaxf(t0, fmaxf(sc[nt][0], sc[nt][1]));
            t1 = fmaxf(t1, fmaxf(sc[nt][2], sc[nt][3]));
        }
        t0 = fmaxf(t0, __shfl_xor_sync(0xffffffffu, t0, 1));
        t0 = fmaxf(t0, __shfl_xor_sync(0xffffffffu, t0, 2));
        t1 = fmaxf(t1, __shfl_xor_sync(0xffffffffu, t1, 1));
        t1 = fmaxf(t1, __shfl_xor_sync(0xffffffffu, t1, 2));

        float nm0 = fmaxf(mr0, t0), nm1 = fmaxf(mr1, t1);
        float cor0 = __expf(mr0 - nm0), cor1 = __expf(mr1 - nm1);
        mr0 = nm0; mr1 = nm1;

        float s0 = 0.f, s1 = 0.f;
#pragma unroll
        for (int nt = 0; nt < 8; nt++) {
            sc[nt][0] = __expf(sc[nt][0] - nm0);
            sc[nt][1] = __expf(sc[nt][1] - nm0);
            sc[nt][2] = __expf(sc[nt][2] - nm1);
            sc[nt][3] = __expf(sc[nt][3] - nm1);
            s0 += sc[nt][0] + sc[nt][1];
            s1 += sc[nt][2] + sc[nt][3];
        }
        s0 += __shfl_xor_sync(0xffffffffu, s0, 1);
        s0 += __shfl_xor_sync(0xffffffffu, s0, 2);
        s1 += __shfl_xor_sync(0xffffffffu, s1, 1);
        s1 += __shfl_xor_sync(0xffffffffu, s1, 2);
        lr0 = lr0 * cor0 + s0;
        lr1 = lr1 * cor1 + s1;

#pragma unroll
        for (int nt = 0; nt < 8; nt++) {
            o[nt][0] *= cor0; o[nt][1] *= cor0;
            o[nt][2] *= cor1; o[nt][3] *= cor1;
        }

        // 6. P -> Psm (tf32 bits), STS.64, per-warp private rows
#pragma unroll
        for (int nt = 0; nt < 8; nt++) {
            int col = nt * 8 + 2 * (lane & 3);
            *(uint2*)&Psm[r0 * 68 + col] =
                make_uint2(f2tf32(sc[nt][0]), f2tf32(sc[nt][1]));
            *(uint2*)&Psm[(r0 + 8) * 68 + col] =
                make_uint2(f2tf32(sc[nt][2]), f2tf32(sc[nt][3]));
        }
        __syncwarp();

        uint32_t pa[8][4];
#pragma unroll
        for (int ks = 0; ks < 8; ks++) {
            int col = ks * 8 + (lane & 3);
            pa[ks][0] = Psm[r0 * 68 + col];
            pa[ks][1] = Psm[(r0 + 8) * 68 + col];
            pa[ks][2] = Psm[r0 * 68 + col + 4];
            pa[ks][3] = Psm[(r0 + 8) * 68 + col + 4];
        }

        // 7. O += P * V
#pragma unroll
        for (int nt = 0; nt < 8; nt++) {
#pragma unroll
            for (int ks = 0; ks < 8; ks++) {
                int vrow = ks * 8 + (lane & 3);
                uint32_t b0 = Vc[vrow * 72 + nt * 8 + (lane >> 2)];
                uint32_t b1 = Vc[(vrow + 4) * 72 + nt * 8 + (lane >> 2)];
                mma_tf32(o[nt], pa[ks], b0, b1);
            }
        }
    }

    // Normalize, round to tf32 bits (feeds out-proj GEMM), write g_O
    float i0 = 1.f / lr0, i1 = 1.f / lr1;
    int r = q0 + warp * 16 + (lane >> 2);
    size_t ob0 = ((size_t)n * TT + r) * DD + h * SS;
    size_t ob1 = ((size_t)n * TT + r + 8) * DD + h * SS;
#pragma unroll
    for (int nt = 0; nt < 8; nt++) {
        int col = nt * 8 + 2 * (lane & 3);
        *(float2*)&g_O[ob0 + col] = make_float2(
            __uint_as_float(f2tf32(o[nt][0] * i0)),
            __uint_as_float(f2tf32(o[nt][1] * i0)));
        *(float2*)&g_O[ob1 + col] = make_float2(
            __uint_as_float(f2tf32(o[nt][2] * i1)),
            __uint_as_float(f2tf32(o[nt][3] * i1)));
    }
}

// ============================================================================
// Launch
// ============================================================================
extern "C" void kernel_launch(void* const* d_in, const int* in_sizes, int n_in,
                              void* d_out, int out_size)
{
    const float* qseq = (const float*)d_in[0];
    const float* rseq = (const float*)d_in[1];
    const float* mask = (const float*)d_in[2];
    const float* Wq   = (const float*)d_in[3];
    const float* Wk   = (const float*)d_in[4];
    const float* Wv   = (const float*)d_in[5];
    const float* Wo   = (const float*)d_in[6];
    float* out = (float*)d_out;

    const int gemm_smem = 3 * (128 * 36 + 32 * 136) * 4;                // 107520
    const int flash_smem = (2 * 64 * 68 + 2 * 64 * 72 + 128 * 68) * 4;  // 106496
    cudaFuncSetAttribute(gemm_tf32_kernel, cudaFuncAttributeMaxDynamicSharedMemorySize,
                         gemm_smem);
    cudaFuncSetAttribute(flash_kernel, cudaFuncAttributeMaxDynamicSharedMemorySize,
                         flash_smem);

    // Prep: round activations + weights to tf32 bits
    prep_round_act<<<dim3(4096, 1, 2), 256>>>(qseq, rseq);
    prep_round_w<<<dim3(1024, 1, 4), 256>>>(Wq, Wk, Wv, Wo);

    // QKV projections fused into one launch over z
    gemm_tf32_kernel<<<dim3(8, 32, 3), 256, gemm_smem>>>(nullptr, 0);

    // Flash attention
    flash_kernel<<<dim3(16, HH, NB), 256, flash_smem>>>(mask);

    // Output projection -> d_out
    gemm_tf32_kernel<<<dim3(8, 32, 1), 256, gemm_smem>>>(out, 1);
}

// round 7
// speedup vs baseline: 1.9192x; 1.0042x over previous
#include <cuda_runtime.h>
#include <cuda_bf16.h>
#include <cstdint>

// Problem constants
#define NB 2
#define HH 16
#define TT 2048
#define DD 1024
#define SS 64
#define NEG_INF (-1e9f)

// Scratch (device globals; no runtime allocation). All tf32-pre-rounded bits.
// Pair-packed layouts (see round notes):
//  g_Aq/g_Ar/g_O : [m][kpos]   kpos = (k&~7) + pos8(k&7)
//  g_Wr          : [z][(k>>3)*4 + (k&3)][n*2 + ((k>>2)&1)]   (512 x 2048 per z)
//  g_Q/g_K       : [n][h][t][spos]
//  g_V           : [n][h][(t>>3)*4 + (t&3)][s*2 + ((t>>2)&1)] (1024 x 128 per head)
__device__ float g_Q[NB * HH * TT * SS];
__device__ float g_K[NB * HH * TT * SS];
__device__ float g_V[NB * HH * TT * SS];
__device__ float g_O[NB * TT * DD];
__device__ float g_Aq[NB * TT * DD];
__device__ float g_Ar[NB * TT * DD];
__device__ float g_Wr[4 * DD * DD];

__device__ __forceinline__ int pos8(int i) { return (i & 3) * 2 + (i >> 2); }

__device__ __forceinline__ uint32_t f2tf32(float x) {
    uint32_t r;
    asm("cvt.rna.tf32.f32 %0, %1;" : "=r"(r) : "f"(x));
    return r;
}

__device__ __forceinline__ void mma_tf32(float* c, const uint32_t* a, uint32_t b0, uint32_t b1) {
    asm volatile(
        "mma.sync.aligned.m16n8k8.row.col.f32.tf32.tf32.f32 "
        "{%0,%1,%2,%3}, {%4,%5,%6,%7}, {%8,%9}, {%0,%1,%2,%3};\n"
        : "+f"(c[0]), "+f"(c[1]), "+f"(c[2]), "+f"(c[3])
        : "r"(a[0]), "r"(a[1]), "r"(a[2]), "r"(a[3]), "r"(b0), "r"(b1));
}

__device__ __forceinline__ void cp16(void* smem_dst, const void* gsrc) {
    uint32_t d = (uint32_t)__cvta_generic_to_shared(smem_dst);
    asm volatile("cp.async.cg.shared.global [%0], [%1], 16;\n" :: "r"(d), "l"(gsrc));
}
__device__ __forceinline__ void cp_commit() { asm volatile("cp.async.commit_group;\n"); }
__device__ __forceinline__ void cp_wait0()  { asm volatile("cp.async.wait_group 0;\n"); }
__device__ __forceinline__ void cp_wait1()  { asm volatile("cp.async.wait_group 1;\n"); }
__device__ __forceinline__ void l2_prefetch(const void* p) {
    asm volatile("prefetch.global.L2 [%0];" :: "l"(p));
}

// ============================================================================
// Prep: round + pair-pack activations. Thread handles 8 consecutive k.
// ============================================================================
__global__ void __launch_bounds__(256) prep_round_act(const float* __restrict__ q,
                                                      const float* __restrict__ r) {
    const float* src = blockIdx.z ? r : q;
    float* dst = blockIdx.z ? g_Ar : g_Aq;
    size_t idx = (size_t)blockIdx.x * 256 + threadIdx.x;   // 524288 per tensor
    size_t m = idx >> 7;
    int k0 = (int)(idx & 127) * 8;
    float4 v0 = *(const float4*)(src + m * DD + k0);
    float4 v1 = *(const float4*)(src + m * DD + k0 + 4);
    uint4 oa, ob;
    oa.x = f2tf32(v0.x); oa.y = f2tf32(v1.x); oa.z = f2tf32(v0.y); oa.w = f2tf32(v1.y);
    ob.x = f2tf32(v0.z); ob.y = f2tf32(v1.z); ob.z = f2tf32(v0.w); ob.w = f2tf32(v1.w);
    *(uint4*)(dst + m * DD + k0) = oa;
    *(uint4*)(dst + m * DD + k0 + 4) = ob;
}

// Prep: round + pack weights: [pr][n*2+half], pr=(k>>3)*4+(k&3), half=(k>>2)&1
__global__ void __launch_bounds__(256) prep_round_w(
    const float* __restrict__ W0, const float* __restrict__ W1,
    const float* __restrict__ W2, const float* __restrict__ W3) {
    const int z = blockIdx.z;
    const float* W = (z == 0) ? W0 : (z == 1) ? W1 : (z == 2) ? W2 : W3;
    float* dst = g_Wr + (size_t)z * DD * DD;
    size_t idx = (size_t)blockIdx.x * 256 + threadIdx.x;   // 131072 per weight
    int pr = (int)(idx >> 8);            // 0..511
    int n0 = (int)(idx & 255) * 4;
    int k = (pr >> 2) * 8 + (pr & 3);
    float4 a = *(const float4*)(W + (size_t)k * DD + n0);
    float4 b = *(const float4*)(W + (size_t)(k + 4) * DD + n0);
    uint4 oa, ob;
    oa.x = f2tf32(a.x); oa.y = f2tf32(b.x); oa.z = f2tf32(a.y); oa.w = f2tf32(b.y);
    ob.x = f2tf32(a.z); ob.y = f2tf32(b.z); ob.z = f2tf32(a.w); ob.w = f2tf32(b.w);
    *(uint4*)(dst + (size_t)pr * 2048 + n0 * 2) = oa;
    *(uint4*)(dst + (size_t)pr * 2048 + n0 * 2 + 4) = ob;
}

// ============================================================================
// TF32 GEMM v5: pair-packed operands -> all fragment reads are LDS.64.
// 3-stage cp.async pipeline. A pitch 40, B pitch 264 (conflict-free LDS.64).
// mode 0: z in {0,1,2}: A = g_Aq/g_Ar, B = g_Wr[z] -> scatter packed Q/K/V
// mode 1: A = g_O (packed), B = g_Wr[3] -> plain f32 row-major into outp
// ============================================================================
__global__ void __launch_bounds__(256, 2) gemm_tf32_kernel(
    float* __restrict__ outp, int mode)
{
    constexpr int AP = 40;     // A smem pitch (u32)
    constexpr int BP2 = 264;   // B smem pitch (u32), 256 data + 8 pad
    constexpr int STG = 128 * AP + 16 * BP2;   // 9344 u32 per stage
    extern __shared__ uint32_t sm[];           // 3 stages

    const int z = blockIdx.z;
    const float* A = (mode == 1) ? g_O : (z == 0 ? g_Aq : g_Ar);
    const float* B = g_Wr + (size_t)((mode == 1) ? 3 : z) * DD * DD;

    const int tid = threadIdx.x;
    const int lane = tid & 31, warp = tid >> 5;
    const int la3 = lane & 3, q4 = lane >> 2;
    const int wm = warp & 3, wn = warp >> 2;  // 4 x 2 warp grid
    const int m0 = blockIdx.y * 128, n0 = blockIdx.x * 128;

    float c[2][8][4];
#pragma unroll
    for (int mt = 0; mt < 2; mt++)
#pragma unroll
        for (int nt = 0; nt < 8; nt++)
#pragma unroll
            for (int i = 0; i < 4; i++) c[mt][nt][i] = 0.f;

    auto prefetch = [&](int k0, int stg) {
        uint32_t* Ad = sm + stg * STG;
        uint32_t* Bd = Ad + 128 * AP;
#pragma unroll
        for (int i = 0; i < 4; i++) {
            int lin = tid + i * 256;
            int r = lin >> 3, ch = lin & 7;
            cp16(Ad + r * AP + ch * 4, A + (size_t)(m0 + r) * DD + k0 + ch * 4);
        }
        // B: 16 pair-rows x 256 floats (64 chunks each)
#pragma unroll
        for (int i = 0; i < 4; i++) {
            int lin = tid + i * 256;
            int r = lin >> 6, ch = lin & 63;
            cp16(Bd + r * BP2 + ch * 4,
                 B + (size_t)(k0 / 2 + r) * 2048 + n0 * 2 + ch * 4);
        }
        cp_commit();
    };

    prefetch(0, 0);
    prefetch(32, 1);

    for (int t = 0; t < 32; t++) {
        cp_wait1();
        __syncthreads();
        if (t + 2 < 32) prefetch((t + 2) * 32, (t + 2) % 3);
        else cp_commit();

        const uint32_t* Ab = sm + (t % 3) * STG;
        const uint32_t* Bb = Ab + 128 * AP;
#pragma unroll
        for (int ks = 0; ks < 32; ks += 8) {
            uint32_t a[2][4];
#pragma unroll
            for (int mt = 0; mt < 2; mt++) {
                int r = wm * 32 + mt * 16 + q4;
                uint2 lo = *(const uint2*)&Ab[r * AP + ks + la3 * 2];
                uint2 hi = *(const uint2*)&Ab[(r + 8) * AP + ks + la3 * 2];
                a[mt][0] = lo.x; a[mt][2] = lo.y;
                a[mt][1] = hi.x; a[mt][3] = hi.y;
            }
            const int prb = (ks >> 1) + la3;   // B pair-row for this lane
#pragma unroll
            for (int nt = 0; nt < 8; nt++) {
                int cc = wn * 64 + nt * 8 + q4;
                uint2 b = *(const uint2*)&Bb[prb * BP2 + cc * 2];
                mma_tf32(c[0][nt], a[0], b.x, b.y);
                mma_tf32(c[1][nt], a[1], b.x, b.y);
            }
        }
    }

    // Epilogue
    const float scale = (mode == 0 && z == 0) ? 0.125f : 1.0f;
#pragma unroll
    for (int mt = 0; mt < 2; mt++) {
        int row = m0 + wm * 32 + mt * 16 + q4;
#pragma unroll
        for (int nt = 0; nt < 8; nt++) {
            int col = n0 + wn * 64 + nt * 8 + 2 * la3;
#pragma unroll
            for (int half = 0; half < 2; half++) {
                int r = row + half * 8;
                float v0 = c[mt][nt][half * 2 + 0] * scale;
                float v1 = c[mt][nt][half * 2 + 1] * scale;
                if (mode == 0) {
                    uint32_t u0 = f2tf32(v0), u1 = f2tf32(v1);
                    int nn = r >> 11, t = r & 2047;
                    int h = col >> 6, s = col & 63;
                    if (z == 2) {
                        // V packing: [pr][s*2+half2]
                        float* dst = g_V + ((size_t)(nn * HH + h)) * (TT * SS) +
                                     (size_t)((t >> 3) * 4 + (t & 3)) * 128 +
                                     ((t >> 2) & 1);
                        dst[s * 2]       = __uint_as_float(u0);
                        dst[(s + 1) * 2] = __uint_as_float(u1);
                    } else {
                        float* dstb = (z == 0) ? g_Q : g_K;
                        size_t base = (((size_t)(nn * HH + h) * TT) + t) * SS;
                        int g = s & ~7;
                        dstb[base + g + pos8(s & 7)]       = __uint_as_float(u0);
                        dstb[base + g + pos8((s + 1) & 7)] = __uint_as_float(u1);
                    }
                } else {
                    *(float2*)&outp[(size_t)r * DD + col] = make_float2(v0, v1);
                }
            }
        }
    }
}

// ============================================================================
// Flash attention v5: all K/V/Q fragment reads are LDS.64 (paired layouts).
// K pitch 72, V pitch 136, P/Q staging pitch 68.
// ============================================================================
__global__ void __launch_bounds__(256, 2) flash_kernel(const float* __restrict__ mask)
{
    extern __shared__ float sh[];
    float* Kb = sh;                     // [2][64*72]
    float* Vb = sh + 2 * 64 * 72;       // [2][32*136]
    uint32_t* Psm = (uint32_t*)(sh + 2 * 64 * 72 + 2 * 32 * 136);  // [128*68]

    const int tid = threadIdx.x;
    const int lane = tid & 31, warp = tid >> 5;
    const int la3 = lane & 3, q4 = lane >> 2;
    const int qt = blockIdx.x, h = blockIdx.y, n = blockIdx.z;
    const int q0 = qt * 128;
    const size_t headbase = ((size_t)(n * HH + h)) * TT * SS;
    const float* Vhead = g_V + headbase;   // packed [1024][128]

    auto prefetchKV = [&](int j, int stg) {
        const int k0 = j * 64;
        float* Kd = Kb + stg * 64 * 72;
        float* Vd = Vb + stg * 32 * 136;
#pragma unroll
        for (int i = 0; i < 4; i++) {
            int lin = tid + i * 256;
            int r = lin >> 4, c16 = lin & 15;
            cp16(Kd + r * 72 + c16 * 4, &g_K[headbase + (size_t)(k0 + r) * SS + c16 * 4]);
        }
        // V: 32 pair-rows x 128 floats (32 chunks each)
#pragma unroll
        for (int i = 0; i < 4; i++) {
            int lin = tid + i * 256;
            int r = lin >> 5, ch = lin & 31;
            cp16(Vd + r * 136 + ch * 4, Vhead + (size_t)(k0 / 2 + r) * 128 + ch * 4);
        }
        cp_commit();
    };

    const float* mwarp =
        mask + (((size_t)(n * HH + h)) * TT + q0 + warp * 16) * TT;
    const float* mbase = mwarp + (size_t)q4 * TT;

    prefetchKV(0, 0);
#pragma unroll
    for (int i = 0; i < 8; i++) {
        int lin = tid + i * 256;
        int r = lin >> 4, c16 = lin & 15;
        cp16(Psm + r * 68 + c16 * 4, &g_Q[headbase + (size_t)(q0 + r) * SS + c16 * 4]);
    }
    cp_commit();
    l2_prefetch(mwarp + (size_t)(lane >> 1) * TT + (lane & 1) * 32);
    cp_wait0();
    __syncthreads();

    const int r0 = warp * 16 + q4;

    // Q fragments (packed cols -> LDS.64 pairs)
    uint32_t qa[8][4];
#pragma unroll
    for (int ks = 0; ks < 8; ks++) {
        uint2 lo = *(const uint2*)&Psm[r0 * 68 + ks * 8 + la3 * 2];
        uint2 hi = *(const uint2*)&Psm[(r0 + 8) * 68 + ks * 8 + la3 * 2];
        qa[ks][0] = lo.x; qa[ks][2] = lo.y;
        qa[ks][1] = hi.x; qa[ks][3] = hi.y;
    }

    float o[8][4];
#pragma unroll
    for (int nt = 0; nt < 8; nt++)
#pragma unroll
        for (int i = 0; i < 4; i++) o[nt][i] = 0.f;
    float mr0 = -INFINITY, mr1 = -INFINITY;
    float lr0 = 0.f, lr1 = 0.f;

    for (int j = 0; j < 32; j++) {
        const int k0 = j * 64;

        // Mask -> score init (issued before the KV wait)
        float sc[8][4];
#pragma unroll
        for (int nt = 0; nt < 8; nt++) {
            int col = k0 + nt * 8 + 2 * la3;
            float2 m0v = *(const float2*)(mbase + col);
            float2 m1v = *(const float2*)(mbase + (size_t)8 * TT + col);
            sc[nt][0] = m0v.x * NEG_INF;
            sc[nt][1] = m0v.y * NEG_INF;
            sc[nt][2] = m1v.x * NEG_INF;
            sc[nt][3] = m1v.y * NEG_INF;
        }

        cp_wait0();
        __syncthreads();

        if (j + 1 < 32) {
            prefetchKV(j + 1, (j + 1) & 1);
            l2_prefetch(mwarp + (size_t)(lane >> 1) * TT + (j + 1) * 64 + (lane & 1) * 32);
        }

        const uint32_t* Kc = (const uint32_t*)(Kb + (j & 1) * 64 * 72);
        const uint32_t* Vc = (const uint32_t*)(Vb + (j & 1) * 32 * 136);

        // sc += Q * K^T  (paired K frags: LDS.64)
#pragma unroll
        for (int nt = 0; nt < 8; nt++) {
            int krow = nt * 8 + q4;
#pragma unroll
            for (int ks = 0; ks < 8; ks++) {
                uint2 b = *(const uint2*)&Kc[krow * 72 + ks * 8 + la3 * 2];
                mma_tf32(sc[nt], qa[ks], b.x, b.y);
            }
        }

        // Online softmax
        float t0 = -INFINITY, t1 = -INFINITY;
#pragma unroll
        for (int nt = 0; nt < 8; nt++) {
            t0 = fmaxf(t0, fmaxf(sc[nt][0], sc[nt][1]));
            t1 = fmaxf(t1, fmaxf(sc[nt][2], sc[nt][3]));
        }
        t0 = fmaxf(t0, __shfl_xor_sync(0xffffffffu, t0, 1));
        t0 = fmaxf(t0, __shfl_xor_sync(0xffffffffu, t0, 2));
        t1 = fmaxf(t1, __shfl_xor_sync(0xffffffffu, t1, 1));
        t1 = fmaxf(t1, __shfl_xor_sync(0xffffffffu, t1, 2));

        float nm0 = fmaxf(mr0, t0), nm1 = fmaxf(mr1, t1);
        float cor0 = __expf(mr0 - nm0), cor1 = __expf(mr1 - nm1);
        mr0 = nm0; mr1 = nm1;

        float s0 = 0.f, s1 = 0.f;
#pragma unroll
        for (int nt = 0; nt < 8; nt++) {
            sc[nt][0] = __expf(sc[nt][0] - nm0);
            sc[nt][1] = __expf(sc[nt][1] - nm0);
            sc[nt][2] = __expf(sc[nt][2] - nm1);
            sc[nt][3] = __expf(sc[nt][3] - nm1);
            s0 += sc[nt][0] + sc[nt][1];
            s1 += sc[nt][2] + sc[nt][3];
        }
        s0 += __shfl_xor_sync(0xffffffffu, s0, 1);
        s0 += __shfl_xor_sync(0xffffffffu, s0, 2);
        s1 += __shfl_xor_sync(0xffffffffu, s1, 1);
        s1 += __shfl_xor_sync(0xffffffffu, s1, 2);
        lr0 = lr0 * cor0 + s0;
        lr1 = lr1 * cor1 + s1;

#pragma unroll
        for (int nt = 0; nt < 8; nt++) {
            o[nt][0] *= cor0; o[nt][1] *= cor0;
            o[nt][2] *= cor1; o[nt][3] *= cor1;
        }

        // P -> Psm (linear layout), STS.64
#pragma unroll
        for (int nt = 0; nt < 8; nt++) {
            int col = nt * 8 + 2 * la3;
            *(uint2*)&Psm[r0 * 68 + col] =
                make_uint2(f2tf32(sc[nt][0]), f2tf32(sc[nt][1]));
            *(uint2*)&Psm[(r0 + 8) * 68 + col] =
                make_uint2(f2tf32(sc[nt][2]), f2tf32(sc[nt][3]));
        }
        __syncwarp();

        uint32_t pa[8][4];
#pragma unroll
        for (int ks = 0; ks < 8; ks++) {
            int col = ks * 8 + la3;
            pa[ks][0] = Psm[r0 * 68 + col];
            pa[ks][1] = Psm[(r0 + 8) * 68 + col];
            pa[ks][2] = Psm[r0 * 68 + col + 4];
            pa[ks][3] = Psm[(r0 + 8) * 68 + col + 4];
        }

        // O += P * V  (paired V frags: LDS.64)
#pragma unroll
        for (int nt = 0; nt < 8; nt++) {
            int vcol = (nt * 8 + q4) * 2;
#pragma unroll
            for (int ks = 0; ks < 8; ks++) {
                uint2 b = *(const uint2*)&Vc[(ks * 4 + la3) * 136 + vcol];
                mma_tf32(o[nt], pa[ks], b.x, b.y);
            }
        }
    }

    // Normalize, round, write g_O in PACKED col layout (feeds out-proj GEMM)
    float i0 = 1.f / lr0, i1 = 1.f / lr1;
    int r = q0 + warp * 16 + q4;
    size_t ob0 = ((size_t)n * TT + r) * DD;
    size_t ob1 = ((size_t)n * TT + r + 8) * DD;
#pragma unroll
    for (int nt = 0; nt < 8; nt++) {
        int gb = h * SS + nt * 8;           // group base (multiple of 8)
        int i = 2 * la3;
        int p0 = gb + pos8(i), p1 = gb + pos8(i + 1);
        g_O[ob0 + p0] = __uint_as_float(f2tf32(o[nt][0] * i0));
        g_O[ob0 + p1] = __uint_as_float(f2tf32(o[nt][1] * i0));
        g_O[ob1 + p0] = __uint_as_float(f2tf32(o[nt][2] * i1));
        g_O[ob1 + p1] = __uint_as_float(f2tf32(o[nt][3] * i1));
    }
}

// ============================================================================
// Launch
// ============================================================================
extern "C" void kernel_launch(void* const* d_in, const int* in_sizes, int n_in,
                              void* d_out, int out_size)
{
    const float* qseq = (const float*)d_in[0];
    const float* rseq = (const float*)d_in[1];
    const float* mask = (const float*)d_in[2];
    const float* Wq   = (const float*)d_in[3];
    const float* Wk   = (const float*)d_in[4];
    const float* Wv   = (const float*)d_in[5];
    const float* Wo   = (const float*)d_in[6];
    float* out = (float*)d_out;

    const int gemm_smem = 3 * (128 * 40 + 16 * 264) * 4;                 // 112128
    const int flash_smem = (2 * 64 * 72 + 2 * 32 * 136 + 128 * 68) * 4;  // 106496
    cudaFuncSetAttribute(gemm_tf32_kernel, cudaFuncAttributeMaxDynamicSharedMemorySize,
                         gemm_smem);
    cudaFuncSetAttribute(flash_kernel, cudaFuncAttributeMaxDynamicSharedMemorySize,
                         flash_smem);

    // Prep: round + pack activations and weights
    prep_round_act<<<dim3(2048, 1, 2), 256>>>(qseq, rseq);
    prep_round_w<<<dim3(512, 1, 4), 256>>>(Wq, Wk, Wv, Wo);

    // QKV projections fused into one launch over z
    gemm_tf32_kernel<<<dim3(8, 32, 3), 256, gemm_smem>>>(nullptr, 0);

    // Flash attention
    flash_kernel<<<dim3(16, HH, NB), 256, flash_smem>>>(mask);

    // Output projection -> d_out
    gemm_tf32_kernel<<<dim3(8, 32, 1), 256, gemm_smem>>>(out, 1);
}

// round 9
// speedup vs baseline: 3.2557x; 1.6964x over previous
#include <cuda_runtime.h>
#include <cuda_fp16.h>
#include <cstdint>

// Problem constants
#define NB 2
#define HH 16
#define TT 2048
#define DD 1024
#define SS 64
#define NEG_INF (-1e9f)

// Scratch (device globals; no runtime allocation). All fp16, pre-rounded.
// Packings (pos8 on half2 pairs within 16-element k-groups):
//  g_Aq/g_Ar/g_Oh : [m][(k&~15) + pos8((k>>1)&7)*2 + (k&1)]
//  g_Wh           : [z][kg=k>>4][n][8 half2 in pos8 order]
//  g_Qh/g_Kh      : [n][h][t][(s&~15) + pos8((s>>1)&7)*2 + (s&1)]
//  g_Vh           : [n][h][tg=t>>4][s][8 half2: (V[2j][s],V[2j+1][s]) at pos8(j)]
__device__ __half g_Qh[NB * HH * TT * SS];
__device__ __half g_Kh[NB * HH * TT * SS];
__device__ __half g_Vh[NB * HH * TT * SS];
__device__ __half g_Oh[NB * TT * DD];
__device__ __half g_Aq[NB * TT * DD];
__device__ __half g_Ar[NB * TT * DD];
__device__ __half g_Wh[4 * DD * DD];

__device__ __forceinline__ int pos8(int j) { return (j & 3) * 2 + (j >> 2); }

__device__ __forceinline__ uint32_t h2u(float a, float b) {
    __half2 h = __floats2half2_rn(a, b);
    return *reinterpret_cast<uint32_t*>(&h);
}

__device__ __forceinline__ void mma_f16(float* c, const uint32_t* a,
                                        uint32_t b0, uint32_t b1) {
    asm volatile(
        "mma.sync.aligned.m16n8k16.row.col.f32.f16.f16.f32 "
        "{%0,%1,%2,%3}, {%4,%5,%6,%7}, {%8,%9}, {%0,%1,%2,%3};\n"
        : "+f"(c[0]), "+f"(c[1]), "+f"(c[2]), "+f"(c[3])
        : "r"(a[0]), "r"(a[1]), "r"(a[2]), "r"(a[3]), "r"(b0), "r"(b1));
}

__device__ __forceinline__ void cp16(void* smem_dst, const void* gsrc) {
    uint32_t d = (uint32_t)__cvta_generic_to_shared(smem_dst);
    asm volatile("cp.async.cg.shared.global [%0], [%1], 16;\n" :: "r"(d), "l"(gsrc));
}
__device__ __forceinline__ void cp_commit() { asm volatile("cp.async.commit_group;\n"); }
__device__ __forceinline__ void cp_wait0()  { asm volatile("cp.async.wait_group 0;\n"); }
__device__ __forceinline__ void cp_wait1()  { asm volatile("cp.async.wait_group 1;\n"); }
__device__ __forceinline__ void l2_prefetch(const void* p) {
    asm volatile("prefetch.global.L2 [%0];" :: "l"(p));
}

// ============================================================================
// Prep: activations f32 -> packed fp16. Thread handles 16 consecutive k.
// ============================================================================
__global__ void __launch_bounds__(256) prep_act(const float* __restrict__ q,
                                                const float* __restrict__ r) {
    const float* src = blockIdx.z ? r : q;
    __half* dst = blockIdx.z ? g_Ar : g_Aq;
    size_t idx = (size_t)blockIdx.x * 256 + threadIdx.x;   // 262144 per tensor
    size_t m = idx >> 6;
    int k0 = (int)(idx & 63) * 16;
    float f[16];
    const float* s = src + m * DD + k0;
#pragma unroll
    for (int i = 0; i < 4; i++) *(float4*)(f + i * 4) = *(const float4*)(s + i * 4);
    uint32_t hh[8];
#pragma unroll
    for (int j = 0; j < 8; j++) hh[pos8(j)] = h2u(f[2 * j], f[2 * j + 1]);
    __half* d = dst + m * DD + k0;
    *(uint4*)d = make_uint4(hh[0], hh[1], hh[2], hh[3]);
    *(uint4*)(d + 8) = make_uint4(hh[4], hh[5], hh[6], hh[7]);
}

// Prep: weights f32 [k][n] -> g_Wh [z][kg][n][8 half2 pos8 order]
__global__ void __launch_bounds__(256) prep_w(
    const float* __restrict__ W0, const float* __restrict__ W1,
    const float* __restrict__ W2, const float* __restrict__ W3) {
    const int z = blockIdx.z;
    const float* W = (z == 0) ? W0 : (z == 1) ? W1 : (z == 2) ? W2 : W3;
    size_t idx = (size_t)blockIdx.x * 256 + threadIdx.x;   // 65536 per weight
    int kg = (int)(idx >> 10), n = (int)(idx & 1023);
    float f[16];
#pragma unroll
    for (int i = 0; i < 16; i++) f[i] = W[(size_t)(kg * 16 + i) * DD + n];
    uint32_t hh[8];
#pragma unroll
    for (int j = 0; j < 8; j++) hh[pos8(j)] = h2u(f[2 * j], f[2 * j + 1]);
    __half* d = g_Wh + (size_t)z * DD * DD + ((size_t)kg * 1024 + n) * 16;
    *(uint4*)d = make_uint4(hh[0], hh[1], hh[2], hh[3]);
    *(uint4*)(d + 8) = make_uint4(hh[4], hh[5], hh[6], hh[7]);
}

// ============================================================================
// fp16 GEMM (m16n8k16): C[M,1024] = A * B, BK=32, 3-stage cp.async.
// mode 0: z in {0,1,2}: A = g_Aq/g_Ar, B = g_Wh[z] -> scatter packed Q/K/V fp16
// mode 1: A = g_Oh, B = g_Wh[3] -> f32 row-major into outp
// Smem: A pitch 48 halfs (conflict-free), B [kg][n][8 half2].
// ============================================================================
__global__ void __launch_bounds__(256, 2) gemm_f16_kernel(
    float* __restrict__ outp, int mode)
{
    constexpr int STGH = 128 * 48 + 256 * 16;   // 10240 halfs per stage
    extern __shared__ __half smh[];

    const int z = blockIdx.z;
    const __half* A = (mode == 1) ? g_Oh : (z == 0 ? g_Aq : g_Ar);
    const __half* B = g_Wh + (size_t)((mode == 1) ? 3 : z) * DD * DD;

    const int tid = threadIdx.x;
    const int lane = tid & 31, warp = tid >> 5;
    const int la3 = lane & 3, q4 = lane >> 2;
    const int wm = warp & 3, wn = warp >> 2;  // 4 x 2 warp grid
    const int m0 = blockIdx.y * 128, n0 = blockIdx.x * 128;

    float c[2][8][4];
#pragma unroll
    for (int mt = 0; mt < 2; mt++)
#pragma unroll
        for (int nt = 0; nt < 8; nt++)
#pragma unroll
            for (int i = 0; i < 4; i++) c[mt][nt][i] = 0.f;

    auto prefetch = [&](int k0, int stg) {
        __half* base = smh + stg * STGH;
        // A: 128 rows x 32 halfs (4 chunks of 8)
#pragma unroll
        for (int i = 0; i < 2; i++) {
            int lin = tid + i * 256;
            int r = lin >> 2, cc = lin & 3;
            cp16(base + r * 48 + cc * 8, A + (size_t)(m0 + r) * DD + k0 + cc * 8);
        }
        // B: 2 kg x 128 n x 16 halfs (2 chunks)
#pragma unroll
        for (int i = 0; i < 2; i++) {
            int lin = tid + i * 256;
            int kgl = lin >> 8, n = (lin >> 1) & 127, hf = lin & 1;
            cp16(base + 6144 + (kgl * 128 + n) * 16 + hf * 8,
                 B + ((size_t)((k0 >> 4) + kgl) * 1024 + n0 + n) * 16 + hf * 8);
        }
        cp_commit();
    };

    prefetch(0, 0);
    prefetch(32, 1);

    for (int t = 0; t < 32; t++) {
        cp_wait1();
        __syncthreads();
        if (t + 2 < 32) prefetch((t + 2) * 32, (t + 2) % 3);
        else cp_commit();

        const __half* Ab = smh + (t % 3) * STGH;
        const __half* Bb = Ab + 6144;
#pragma unroll
        for (int kg = 0; kg < 2; kg++) {
            uint32_t a[2][4];
#pragma unroll
            for (int mt = 0; mt < 2; mt++) {
                int r = wm * 32 + mt * 16 + q4;
                uint2 lo = *(const uint2*)(Ab + r * 48 + kg * 16 + 4 * la3);
                uint2 hi = *(const uint2*)(Ab + (r + 8) * 48 + kg * 16 + 4 * la3);
                a[mt][0] = lo.x; a[mt][2] = lo.y;
                a[mt][1] = hi.x; a[mt][3] = hi.y;
            }
#pragma unroll
            for (int nt = 0; nt < 8; nt++) {
                int cc = wn * 64 + nt * 8 + q4;
                uint2 b = *(const uint2*)(Bb + (kg * 128 + cc) * 16 + 4 * la3);
                mma_f16(c[0][nt], a[0], b.x, b.y);
                mma_f16(c[1][nt], a[1], b.x, b.y);
            }
        }
    }

    // Epilogue
    const float scale = (mode == 0 && z == 0) ? 0.125f : 1.0f;
#pragma unroll
    for (int mt = 0; mt < 2; mt++) {
        int row = m0 + wm * 32 + mt * 16 + q4;
#pragma unroll
        for (int nt = 0; nt < 8; nt++) {
            int col = n0 + wn * 64 + nt * 8 + 2 * la3;
#pragma unroll
            for (int half = 0; half < 2; half++) {
                int r = row + half * 8;
                float v0 = c[mt][nt][half * 2 + 0] * scale;
                float v1 = c[mt][nt][half * 2 + 1] * scale;
                if (mode == 1) {
                    *(float2*)&outp[(size_t)r * DD + col] = make_float2(v0, v1);
                } else {
                    int nn = r >> 11, t = r & 2047;
                    int h = col >> 6, s = col & 63;
                    size_t hb = (size_t)(nn * HH + h) * TT * SS;   // half units
                    if (z == 2) {
                        // V packing: [tg][s][pos8((t>>1)&7)] half2, half (t&1)
                        int p = pos8((t >> 1) & 7);
                        size_t h2i = hb / 2 + ((size_t)(t >> 4) * 64 + s) * 8 + p;
                        g_Vh[h2i * 2 + (t & 1)]      = __float2half_rn(v0);
                        g_Vh[h2i * 2 + 16 + (t & 1)] = __float2half_rn(v1);
                    } else {
                        __half* dstb = (z == 0) ? g_Qh : g_Kh;
                        int j = (s >> 1) & 7;
                        size_t ha = hb + (size_t)t * SS + (s & ~15) + 2 * pos8(j);
                        *(uint32_t*)&dstb[ha] = h2u(v0, v1);
                    }
                }
            }
        }
    }
}

// ============================================================================
// Flash attention fp16: m16n8k16, P stays in registers (accumulator->A frag),
// all K/V/Q fragment reads are single LDS.64.
// Smem: K [2][64*80], V [2][4096], Q [128*80]  (halfs)
// ============================================================================
__global__ void __launch_bounds__(256, 2) flash_kernel(const float* __restrict__ mask)
{
    extern __shared__ __half sh[];
    __half* Ksm = sh;              // 2 x 5120
    __half* Vsm = sh + 10240;      // 2 x 4096
    __half* Qsm = sh + 18432;      // 10240

    const int tid = threadIdx.x;
    const int lane = tid & 31, warp = tid >> 5;
    const int la3 = lane & 3, q4 = lane >> 2;
    const int qt = blockIdx.x, h = blockIdx.y, n = blockIdx.z;
    const int q0 = qt * 128;
    const size_t headbase = ((size_t)(n * HH + h)) * TT * SS;  // half units

    auto prefetchKV = [&](int j, int stg) {
        const int k0 = j * 64;
#pragma unroll
        for (int i = 0; i < 2; i++) {
            int lin = tid + i * 256;
            int r = lin >> 3, cc = lin & 7;
            cp16(Ksm + stg * 5120 + r * 80 + cc * 8,
                 g_Kh + headbase + (size_t)(k0 + r) * SS + cc * 8);
        }
#pragma unroll
        for (int i = 0; i < 2; i++) {
            int lin = tid + i * 256;
            cp16(Vsm + stg * 4096 + lin * 8, g_Vh + headbase + (size_t)j * 4096 + lin * 8);
        }
        cp_commit();
    };

    const float* mwarp =
        mask + (((size_t)(n * HH + h)) * TT + q0 + warp * 16) * TT;
    const float* mbase = mwarp + (size_t)q4 * TT;

    prefetchKV(0, 0);
#pragma unroll
    for (int i = 0; i < 4; i++) {
        int lin = tid + i * 256;
        int r = lin >> 3, cc = lin & 7;
        cp16(Qsm + r * 80 + cc * 8, g_Qh + headbase + (size_t)(q0 + r) * SS + cc * 8);
    }
    cp_commit();
    l2_prefetch(mwarp + (size_t)(lane >> 1) * TT + (lane & 1) * 32);
    cp_wait0();
    __syncthreads();

    const int r0 = warp * 16 + q4;

    // Q fragments: 4 k-steps of 16, each LDS.64 pair
    uint32_t qa[4][4];
#pragma unroll
    for (int ks = 0; ks < 4; ks++) {
        uint2 lo = *(const uint2*)(Qsm + r0 * 80 + ks * 16 + 4 * la3);
        uint2 hi = *(const uint2*)(Qsm + (r0 + 8) * 80 + ks * 16 + 4 * la3);
        qa[ks][0] = lo.x; qa[ks][2] = lo.y;
        qa[ks][1] = hi.x; qa[ks][3] = hi.y;
    }

    float o[8][4];
#pragma unroll
    for (int nt = 0; nt < 8; nt++)
#pragma unroll
        for (int i = 0; i < 4; i++) o[nt][i] = 0.f;
    float mr0 = -INFINITY, mr1 = -INFINITY;
    float lr0 = 0.f, lr1 = 0.f;

    for (int j = 0; j < 32; j++) {
        const int k0 = j * 64;

        // Mask -> score init (LDGs issue before KV wait; latency overlapped)
        float sc[8][4];
#pragma unroll
        for (int nt = 0; nt < 8; nt++) {
            int col = k0 + nt * 8 + 2 * la3;
            float2 m0v = *(const float2*)(mbase + col);
            float2 m1v = *(const float2*)(mbase + (size_t)8 * TT + col);
            sc[nt][0] = m0v.x * NEG_INF;
            sc[nt][1] = m0v.y * NEG_INF;
            sc[nt][2] = m1v.x * NEG_INF;
            sc[nt][3] = m1v.y * NEG_INF;
        }

        cp_wait0();
        __syncthreads();

        if (j + 1 < 32) {
            prefetchKV(j + 1, (j + 1) & 1);
            l2_prefetch(mwarp + (size_t)(lane >> 1) * TT + (j + 1) * 64 + (lane & 1) * 32);
        }

        const __half* Kc = Ksm + (j & 1) * 5120;
        const __half* Vc = Vsm + (j & 1) * 4096;

        // sc += Q * K^T
#pragma unroll
        for (int nt = 0; nt < 8; nt++) {
            int key = nt * 8 + q4;
#pragma unroll
            for (int ks = 0; ks < 4; ks++) {
                uint2 b = *(const uint2*)(Kc + key * 80 + ks * 16 + 4 * la3);
                mma_f16(sc[nt], qa[ks], b.x, b.y);
            }
        }

        // Online softmax (f32)
        float t0 = -INFINITY, t1 = -INFINITY;
#pragma unroll
        for (int nt = 0; nt < 8; nt++) {
            t0 = fmaxf(t0, fmaxf(sc[nt][0], sc[nt][1]));
            t1 = fmaxf(t1, fmaxf(sc[nt][2], sc[nt][3]));
        }
        t0 = fmaxf(t0, __shfl_xor_sync(0xffffffffu, t0, 1));
        t0 = fmaxf(t0, __shfl_xor_sync(0xffffffffu, t0, 2));
        t1 = fmaxf(t1, __shfl_xor_sync(0xffffffffu, t1, 1));
        t1 = fmaxf(t1, __shfl_xor_sync(0xffffffffu, t1, 2));

        float nm0 = fmaxf(mr0, t0), nm1 = fmaxf(mr1, t1);
        float cor0 = __expf(mr0 - nm0), cor1 = __expf(mr1 - nm1);
        mr0 = nm0; mr1 = nm1;

        float s0 = 0.f, s1 = 0.f;
#pragma unroll
        for (int nt = 0; nt < 8; nt++) {
            sc[nt][0] = __expf(sc[nt][0] - nm0);
            sc[nt][1] = __expf(sc[nt][1] - nm0);
            sc[nt][2] = __expf(sc[nt][2] - nm1);
            sc[nt][3] = __expf(sc[nt][3] - nm1);
            s0 += sc[nt][0] + sc[nt][1];
            s1 += sc[nt][2] + sc[nt][3];
        }
        s0 += __shfl_xor_sync(0xffffffffu, s0, 1);
        s0 += __shfl_xor_sync(0xffffffffu, s0, 2);
        s1 += __shfl_xor_sync(0xffffffffu, s1, 1);
        s1 += __shfl_xor_sync(0xffffffffu, s1, 2);
        lr0 = lr0 * cor0 + s0;
        lr1 = lr1 * cor1 + s1;

#pragma unroll
        for (int nt = 0; nt < 8; nt++) {
            o[nt][0] *= cor0; o[nt][1] *= cor0;
            o[nt][2] *= cor1; o[nt][3] *= cor1;
        }

        // O += P * V : P comes straight from sc registers (no smem)
#pragma unroll
        for (int ks = 0; ks < 4; ks++) {
            uint32_t pa[4];
            pa[0] = h2u(sc[2 * ks][0], sc[2 * ks][1]);
            pa[1] = h2u(sc[2 * ks][2], sc[2 * ks][3]);
            pa[2] = h2u(sc[2 * ks + 1][0], sc[2 * ks + 1][1]);
            pa[3] = h2u(sc[2 * ks + 1][2], sc[2 * ks + 1][3]);
#pragma unroll
            for (int nt = 0; nt < 8; nt++) {
                int s = nt * 8 + q4;
                uint2 b = *(const uint2*)(Vc + (ks * 64 + s) * 16 + 4 * la3);
                mma_f16(o[nt], pa, b.x, b.y);
            }
        }
    }

    // Normalize, write g_Oh packed fp16 (feeds out-proj GEMM A)
    float i0 = 1.f / lr0, i1 = 1.f / lr1;
    int r = q0 + warp * 16 + q4;
    size_t ob0 = ((size_t)n * TT + r) * DD;
    size_t ob1 = ((size_t)n * TT + r + 8) * DD;
#pragma unroll
    for (int nt = 0; nt < 8; nt++) {
        int off = h * SS + (nt >> 1) * 16 + 2 * (2 * la3 + (nt & 1));
        *(uint32_t*)&g_Oh[ob0 + off] = h2u(o[nt][0] * i0, o[nt][1] * i0);
        *(uint32_t*)&g_Oh[ob1 + off] = h2u(o[nt][2] * i1, o[nt][3] * i1);
    }
}

// ============================================================================
// Launch
// ============================================================================
extern "C" void kernel_launch(void* const* d_in, const int* in_sizes, int n_in,
                              void* d_out, int out_size)
{
    const float* qseq = (const float*)d_in[0];
    const float* rseq = (const float*)d_in[1];
    const float* mask = (const float*)d_in[2];
    const float* Wq   = (const float*)d_in[3];
    const float* Wk   = (const float*)d_in[4];
    const float* Wv   = (const float*)d_in[5];
    const float* Wo   = (const float*)d_in[6];
    float* out = (float*)d_out;

    const int gemm_smem = 3 * (128 * 48 + 256 * 16) * 2;   // 61440
    const int flash_smem = (18432 + 10240) * 2;            // 57344
    cudaFuncSetAttribute(gemm_f16_kernel, cudaFuncAttributeMaxDynamicSharedMemorySize,
                         gemm_smem);
    cudaFuncSetAttribute(flash_kernel, cudaFuncAttributeMaxDynamicSharedMemorySize,
                         flash_smem);

    // Prep: f32 -> packed fp16
    prep_act<<<dim3(1024, 1, 2), 256>>>(qseq, rseq);
    prep_w<<<dim3(256, 1, 4), 256>>>(Wq, Wk, Wv, Wo);

    // QKV projections fused into one launch over z
    gemm_f16_kernel<<<dim3(8, 32, 3), 256, gemm_smem>>>(nullptr, 0);

    // Flash attention
    flash_kernel<<<dim3(16, HH, NB), 256, flash_smem>>>(mask);

    // Output projection -> d_out
    gemm_f16_kernel<<<dim3(8, 32, 1), 256, gemm_smem>>>(out, 1);
}

// round 12
// speedup vs baseline: 3.3517x; 1.0295x over previous
#include <cuda_runtime.h>
#include <cuda_fp16.h>
#include <cstdint>

// Problem constants
#define NB 2
#define HH 16
#define TT 2048
#define DD 1024
#define SS 64
#define NEG_INF (-1e9f)

// Scratch (device globals; no runtime allocation). All fp16, pre-rounded.
// Packings (pos8 on half2 pairs within 16-element k-groups):
//  g_Aq/g_Ar/g_Oh : [m][(k&~15) + pos8((k>>1)&7)*2 + (k&1)]
//  g_Wh           : [z][kg=k>>4][n][8 half2 in pos8 order]
//  g_Qh/g_Kh      : [n][h][t][(s&~15) + pos8((s>>1)&7)*2 + (s&1)]
//  g_Vh           : [n][h][tg=t>>4][s][8 half2: (V[2j][s],V[2j+1][s]) at pos8(j)]
__device__ __half g_Qh[NB * HH * TT * SS];
__device__ __half g_Kh[NB * HH * TT * SS];
__device__ __half g_Vh[NB * HH * TT * SS];
__device__ __half g_Oh[NB * TT * DD];
__device__ __half g_Aq[NB * TT * DD];
__device__ __half g_Ar[NB * TT * DD];
__device__ __half g_Wh[4 * DD * DD];

__device__ __forceinline__ int pos8(int j) { return (j & 3) * 2 + (j >> 2); }

__device__ __forceinline__ uint32_t h2u(float a, float b) {
    __half2 h = __floats2half2_rn(a, b);
    return *reinterpret_cast<uint32_t*>(&h);
}

__device__ __forceinline__ void mma_f16(float* c, const uint32_t* a,
                                        uint32_t b0, uint32_t b1) {
    asm volatile(
        "mma.sync.aligned.m16n8k16.row.col.f32.f16.f16.f32 "
        "{%0,%1,%2,%3}, {%4,%5,%6,%7}, {%8,%9}, {%0,%1,%2,%3};\n"
        : "+f"(c[0]), "+f"(c[1]), "+f"(c[2]), "+f"(c[3])
        : "r"(a[0]), "r"(a[1]), "r"(a[2]), "r"(a[3]), "r"(b0), "r"(b1));
}

__device__ __forceinline__ void cp16(void* smem_dst, const void* gsrc) {
    uint32_t d = (uint32_t)__cvta_generic_to_shared(smem_dst);
    asm volatile("cp.async.cg.shared.global [%0], [%1], 16;\n" :: "r"(d), "l"(gsrc));
}
__device__ __forceinline__ void l2_prefetch(const void* p) {
    asm volatile("prefetch.global.L2 [%0];" :: "l"(p));
}
__device__ __forceinline__ uint32_t smem_u32(const void* p) {
    return (uint32_t)__cvta_generic_to_shared(p);
}

#define MBAR_INIT(a, c) \
    asm volatile("mbarrier.init.shared.b64 [%0], %1;" :: "r"(a), "r"(c) : "memory")
#define MBAR_ARRIVE(a) \
    asm volatile("mbarrier.arrive.shared.b64 _, [%0];" :: "r"(a) : "memory")
// .noinc: async completion CONSUMES one expected arrival (R10 bug: without
// .noinc the pending count is pre-incremented -> net-zero -> deadlock).
#define CP_MBAR_ARRIVE(a) \
    asm volatile("cp.async.mbarrier.arrive.noinc.shared.b64 [%0];" :: "r"(a) : "memory")
#define MBAR_WAIT(a, par) do {                                                  \
    uint32_t _m = (a), _p = (par);                                              \
    asm volatile("{\n\t.reg .pred P1;\n\t"                                      \
        "WL_%=:\n\t"                                                            \
        "mbarrier.try_wait.parity.acquire.cta.shared::cta.b64 P1, [%0], %1, 0x989680;\n\t" \
        "@P1 bra.uni WD_%=;\n\t"                                                \
        "bra.uni WL_%=;\n\t"                                                    \
        "WD_%=:\n\t}" :: "r"(_m), "r"(_p) : "memory");                          \
} while (0)

// ============================================================================
// Prep: activations f32 -> packed fp16. Thread handles 16 consecutive k.
// ============================================================================
__global__ void __launch_bounds__(256) prep_act(const float* __restrict__ q,
                                                const float* __restrict__ r) {
    const float* src = blockIdx.z ? r : q;
    __half* dst = blockIdx.z ? g_Ar : g_Aq;
    size_t idx = (size_t)blockIdx.x * 256 + threadIdx.x;
    size_t m = idx >> 6;
    int k0 = (int)(idx & 63) * 16;
    float f[16];
    const float* s = src + m * DD + k0;
#pragma unroll
    for (int i = 0; i < 4; i++) *(float4*)(f + i * 4) = *(const float4*)(s + i * 4);
    uint32_t hh[8];
#pragma unroll
    for (int j = 0; j < 8; j++) hh[pos8(j)] = h2u(f[2 * j], f[2 * j + 1]);
    __half* d = dst + m * DD + k0;
    *(uint4*)d = make_uint4(hh[0], hh[1], hh[2], hh[3]);
    *(uint4*)(d + 8) = make_uint4(hh[4], hh[5], hh[6], hh[7]);
}

// Prep: weights f32 [k][n] -> g_Wh [z][kg][n][8 half2 pos8 order]
__global__ void __launch_bounds__(256) prep_w(
    const float* __restrict__ W0, const float* __restrict__ W1,
    const float* __restrict__ W2, const float* __restrict__ W3) {
    const int z = blockIdx.z;
    const float* W = (z == 0) ? W0 : (z == 1) ? W1 : (z == 2) ? W2 : W3;
    size_t idx = (size_t)blockIdx.x * 256 + threadIdx.x;
    int kg = (int)(idx >> 10), n = (int)(idx & 1023);
    float f[16];
#pragma unroll
    for (int i = 0; i < 16; i++) f[i] = W[(size_t)(kg * 16 + i) * DD + n];
    uint32_t hh[8];
#pragma unroll
    for (int j = 0; j < 8; j++) hh[pos8(j)] = h2u(f[2 * j], f[2 * j + 1]);
    __half* d = g_Wh + (size_t)z * DD * DD + ((size_t)kg * 1024 + n) * 16;
    *(uint4*)d = make_uint4(hh[0], hh[1], hh[2], hh[3]);
    *(uint4*)(d + 8) = make_uint4(hh[4], hh[5], hh[6], hh[7]);
}

// ============================================================================
// fp16 GEMM, mbarrier 4-stage pipeline (no __syncthreads in mainloop).
// mode 0: z in {0,1,2}: A = g_Aq/g_Ar, B = g_Wh[z] -> scatter packed Q/K/V fp16
// mode 1: A = g_Oh, B = g_Wh[3] -> f32 row-major into outp
// ============================================================================
#define GSTGH 10240                    // halfs per stage (A 6144 + B 4096)
#define GEMM_SMEM (4 * GSTGH * 2 + 64) // 81984 bytes

__global__ void __launch_bounds__(256, 2) gemm_f16_kernel(
    float* __restrict__ outp, int mode)
{
    extern __shared__ __half smh[];
    const uint32_t mb_full = smem_u32(smh) + 4 * GSTGH * 2;   // 4 x 8B
    const uint32_t mb_empty = mb_full + 32;                   // 4 x 8B

    const int z = blockIdx.z;
    const __half* A = (mode == 1) ? g_Oh : (z == 0 ? g_Aq : g_Ar);
    const __half* B = g_Wh + (size_t)((mode == 1) ? 3 : z) * DD * DD;

    const int tid = threadIdx.x;
    const int lane = tid & 31, warp = tid >> 5;
    const int la3 = lane & 3, q4 = lane >> 2;
    const int wm = warp & 3, wn = warp >> 2;
    const int m0 = blockIdx.y * 128, n0 = blockIdx.x * 128;

    if (tid == 0) {
#pragma unroll
        for (int s = 0; s < 4; s++) {
            MBAR_INIT(mb_full + s * 8, 256);
            MBAR_INIT(mb_empty + s * 8, 256);
        }
    }
    __syncthreads();

    float c[2][8][4];
#pragma unroll
    for (int mt = 0; mt < 2; mt++)
#pragma unroll
        for (int nt = 0; nt < 8; nt++)
#pragma unroll
            for (int i = 0; i < 4; i++) c[mt][nt][i] = 0.f;

    int pstage = 0, pphase = 1;   // producer cursor (first empty-waits pass)
    int cstage = 0, cphase = 0;   // consumer cursor

    auto producer = [&](int t) {
        MBAR_WAIT(mb_empty + pstage * 8, pphase);
        __half* base = smh + pstage * GSTGH;
        const int k0 = t * 32;
#pragma unroll
        for (int i = 0; i < 2; i++) {
            int lin = tid + i * 256;
            int r = lin >> 2, cc = lin & 3;
            cp16(base + r * 48 + cc * 8, A + (size_t)(m0 + r) * DD + k0 + cc * 8);
        }
#pragma unroll
        for (int i = 0; i < 2; i++) {
            int lin = tid + i * 256;
            int kgl = lin >> 8, n = (lin >> 1) & 127, hf = lin & 1;
            cp16(base + 6144 + (kgl * 128 + n) * 16 + hf * 8,
                 B + ((size_t)((k0 >> 4) + kgl) * 1024 + n0 + n) * 16 + hf * 8);
        }
        CP_MBAR_ARRIVE(mb_full + pstage * 8);
        if (++pstage == 4) { pstage = 0; pphase ^= 1; }
    };

    producer(0); producer(1); producer(2);

    for (int t = 0; t < 32; t++) {
        if (t + 3 < 32) producer(t + 3);
        MBAR_WAIT(mb_full + cstage * 8, cphase);

        const __half* Ab = smh + cstage * GSTGH;
        const __half* Bb = Ab + 6144;
#pragma unroll
        for (int kg = 0; kg < 2; kg++) {
            uint32_t a[2][4];
#pragma unroll
            for (int mt = 0; mt < 2; mt++) {
                int r = wm * 32 + mt * 16 + q4;
                uint2 lo = *(const uint2*)(Ab + r * 48 + kg * 16 + 4 * la3);
                uint2 hi = *(const uint2*)(Ab + (r + 8) * 48 + kg * 16 + 4 * la3);
                a[mt][0] = lo.x; a[mt][2] = lo.y;
                a[mt][1] = hi.x; a[mt][3] = hi.y;
            }
#pragma unroll
            for (int nt = 0; nt < 8; nt++) {
                int cc = wn * 64 + nt * 8 + q4;
                uint2 b = *(const uint2*)(Bb + (kg * 128 + cc) * 16 + 4 * la3);
                mma_f16(c[0][nt], a[0], b.x, b.y);
                mma_f16(c[1][nt], a[1], b.x, b.y);
            }
        }
        MBAR_ARRIVE(mb_empty + cstage * 8);
        if (++cstage == 4) { cstage = 0; cphase ^= 1; }
    }

    // Epilogue
    const float scale = (mode == 0 && z == 0) ? 0.125f : 1.0f;
#pragma unroll
    for (int mt = 0; mt < 2; mt++) {
        int row = m0 + wm * 32 + mt * 16 + q4;
#pragma unroll
        for (int nt = 0; nt < 8; nt++) {
            int col = n0 + wn * 64 + nt * 8 + 2 * la3;
#pragma unroll
            for (int half = 0; half < 2; half++) {
                int r = row + half * 8;
                float v0 = c[mt][nt][half * 2 + 0] * scale;
                float v1 = c[mt][nt][half * 2 + 1] * scale;
                if (mode == 1) {
                    *(float2*)&outp[(size_t)r * DD + col] = make_float2(v0, v1);
                } else {
                    int nn = r >> 11, t = r & 2047;
                    int h = col >> 6, s = col & 63;
                    size_t hb = (size_t)(nn * HH + h) * TT * SS;
                    if (z == 2) {
                        int p = pos8((t >> 1) & 7);
                        size_t h2i = hb / 2 + ((size_t)(t >> 4) * 64 + s) * 8 + p;
                        g_Vh[h2i * 2 + (t & 1)]      = __float2half_rn(v0);
                        g_Vh[h2i * 2 + 16 + (t & 1)] = __float2half_rn(v1);
                    } else {
                        __half* dstb = (z == 0) ? g_Qh : g_Kh;
                        int j = (s >> 1) & 7;
                        size_t ha = hb + (size_t)t * SS + (s & ~15) + 2 * pos8(j);
                        *(uint32_t*)&dstb[ha] = h2u(v0, v1);
                    }
                }
            }
        }
    }
}

// ============================================================================
// Flash attention fp16, mbarrier 4-stage K/V pipeline, Q direct to registers,
// deferred l-reduction, ballot-guarded rescale skip.
// Stage: K 5120 halfs (64x80) + V 4096 halfs = 9216 halfs (18432 B).
// ============================================================================
#define FSTGH 9216
#define FLASH_SMEM (4 * FSTGH * 2 + 64)   // 73792 bytes

__global__ void __launch_bounds__(256, 2) flash_kernel(const float* __restrict__ mask)
{
    extern __shared__ __half sh[];
    const uint32_t mb_full = smem_u32(sh) + 4 * FSTGH * 2;
    const uint32_t mb_empty = mb_full + 32;

    const int tid = threadIdx.x;
    const int lane = tid & 31, warp = tid >> 5;
    const int la3 = lane & 3, q4 = lane >> 2;
    const int qt = blockIdx.x, h = blockIdx.y, n = blockIdx.z;
    const int q0 = qt * 128;
    const size_t headbase = ((size_t)(n * HH + h)) * TT * SS;   // half units

    if (tid == 0) {
#pragma unroll
        for (int s = 0; s < 4; s++) {
            MBAR_INIT(mb_full + s * 8, 256);
            MBAR_INIT(mb_empty + s * 8, 256);
        }
    }
    __syncthreads();

    int pstage = 0, pphase = 1;
    int cstage = 0, cphase = 0;

    auto producer = [&](int t) {
        MBAR_WAIT(mb_empty + pstage * 8, pphase);
        __half* Kd = sh + pstage * FSTGH;
        __half* Vd = Kd + 5120;
#pragma unroll
        for (int i = 0; i < 2; i++) {
            int lin = tid + i * 256;
            int r = lin >> 3, cc = lin & 7;
            cp16(Kd + r * 80 + cc * 8,
                 g_Kh + headbase + (size_t)(t * 64 + r) * SS + cc * 8);
        }
#pragma unroll
        for (int i = 0; i < 2; i++) {
            int lin = tid + i * 256;
            cp16(Vd + lin * 8, g_Vh + headbase + (size_t)t * 4096 + lin * 8);
        }
        CP_MBAR_ARRIVE(mb_full + pstage * 8);
        if (++pstage == 4) { pstage = 0; pphase ^= 1; }
    };

    const float* mwarp =
        mask + (((size_t)(n * HH + h)) * TT + q0 + warp * 16) * TT;
    const float* mbase = mwarp + (size_t)q4 * TT;

    const int r0 = warp * 16 + q4;

    // Q fragments straight from gmem (packed layout = native uint2 frags)
    uint32_t qa[4][4];
#pragma unroll
    for (int ks = 0; ks < 4; ks++) {
        const __half* qrow = g_Qh + headbase + (size_t)(q0 + r0) * SS + ks * 16 + 4 * la3;
        uint2 lo = *(const uint2*)qrow;
        uint2 hi = *(const uint2*)(qrow + 8 * SS);
        qa[ks][0] = lo.x; qa[ks][2] = lo.y;
        qa[ks][1] = hi.x; qa[ks][3] = hi.y;
    }

    producer(0); producer(1); producer(2);
    l2_prefetch(mwarp + (size_t)(lane >> 1) * TT + (lane & 1) * 32);

    float o[8][4];
#pragma unroll
    for (int nt = 0; nt < 8; nt++)
#pragma unroll
        for (int i = 0; i < 4; i++) o[nt][i] = 0.f;
    float mr0 = -INFINITY, mr1 = -INFINITY;
    float lr0 = 0.f, lr1 = 0.f;

    for (int j = 0; j < 32; j++) {
        const int k0 = j * 64;

        // Mask -> score init (LDGs issue before any waits)
        float sc[8][4];
#pragma unroll
        for (int nt = 0; nt < 8; nt++) {
            int col = k0 + nt * 8 + 2 * la3;
            float2 m0v = *(const float2*)(mbase + col);
            float2 m1v = *(const float2*)(mbase + (size_t)8 * TT + col);
            sc[nt][0] = m0v.x * NEG_INF;
            sc[nt][1] = m0v.y * NEG_INF;
            sc[nt][2] = m1v.x * NEG_INF;
            sc[nt][3] = m1v.y * NEG_INF;
        }

        if (j + 3 < 32) {
            producer(j + 3);
            l2_prefetch(mwarp + (size_t)(lane >> 1) * TT + (j + 1) * 64 + (lane & 1) * 32);
        }

        MBAR_WAIT(mb_full + cstage * 8, cphase);
        const __half* Kc = sh + cstage * FSTGH;
        const __half* Vc = Kc + 5120;

        // sc += Q * K^T
#pragma unroll
        for (int nt = 0; nt < 8; nt++) {
            int key = nt * 8 + q4;
#pragma unroll
            for (int ks = 0; ks < 4; ks++) {
                uint2 b = *(const uint2*)(Kc + key * 80 + ks * 16 + 4 * la3);
                mma_f16(sc[nt], qa[ks], b.x, b.y);
            }
        }

        // Online softmax; rescale only when the running max changes
        float t0 = -INFINITY, t1 = -INFINITY;
#pragma unroll
        for (int nt = 0; nt < 8; nt++) {
            t0 = fmaxf(t0, fmaxf(sc[nt][0], sc[nt][1]));
            t1 = fmaxf(t1, fmaxf(sc[nt][2], sc[nt][3]));
        }
        t0 = fmaxf(t0, __shfl_xor_sync(0xffffffffu, t0, 1));
        t0 = fmaxf(t0, __shfl_xor_sync(0xffffffffu, t0, 2));
        t1 = fmaxf(t1, __shfl_xor_sync(0xffffffffu, t1, 1));
        t1 = fmaxf(t1, __shfl_xor_sync(0xffffffffu, t1, 2));

        bool need = (t0 > mr0) || (t1 > mr1);
        if (__ballot_sync(0xffffffffu, need)) {
            float nm0 = fmaxf(mr0, t0), nm1 = fmaxf(mr1, t1);
            float cor0 = __expf(mr0 - nm0), cor1 = __expf(mr1 - nm1);
            mr0 = nm0; mr1 = nm1;
            lr0 *= cor0; lr1 *= cor1;
#pragma unroll
            for (int nt = 0; nt < 8; nt++) {
                o[nt][0] *= cor0; o[nt][1] *= cor0;
                o[nt][2] *= cor1; o[nt][3] *= cor1;
            }
        }

        float s0 = 0.f, s1 = 0.f;
#pragma unroll
        for (int nt = 0; nt < 8; nt++) {
            sc[nt][0] = __expf(sc[nt][0] - mr0);
            sc[nt][1] = __expf(sc[nt][1] - mr0);
            sc[nt][2] = __expf(sc[nt][2] - mr1);
            sc[nt][3] = __expf(sc[nt][3] - mr1);
            s0 += sc[nt][0] + sc[nt][1];
            s1 += sc[nt][2] + sc[nt][3];
        }
        lr0 += s0;   // per-lane partial; cross-lane reduce deferred to end
        lr1 += s1;

        // O += P * V : P straight from sc registers
#pragma unroll
        for (int ks = 0; ks < 4; ks++) {
            uint32_t pa[4];
            pa[0] = h2u(sc[2 * ks][0], sc[2 * ks][1]);
            pa[1] = h2u(sc[2 * ks][2], sc[2 * ks][3]);
            pa[2] = h2u(sc[2 * ks + 1][0], sc[2 * ks + 1][1]);
            pa[3] = h2u(sc[2 * ks + 1][2], sc[2 * ks + 1][3]);
#pragma unroll
            for (int nt = 0; nt < 8; nt++) {
                int s = nt * 8 + q4;
                uint2 b = *(const uint2*)(Vc + (ks * 64 + s) * 16 + 4 * la3);
                mma_f16(o[nt], pa, b.x, b.y);
            }
        }

        MBAR_ARRIVE(mb_empty + cstage * 8);
        if (++cstage == 4) { cstage = 0; cphase ^= 1; }
    }

    // Final cross-lane l reduction (deferred from loop)
    lr0 += __shfl_xor_sync(0xffffffffu, lr0, 1);
    lr0 += __shfl_xor_sync(0xffffffffu, lr0, 2);
    lr1 += __shfl_xor_sync(0xffffffffu, lr1, 1);
    lr1 += __shfl_xor_sync(0xffffffffu, lr1, 2);

    // Normalize, write g_Oh packed fp16 (feeds out-proj GEMM A)
    float i0 = 1.f / lr0, i1 = 1.f / lr1;
    int r = q0 + warp * 16 + q4;
    size_t ob0 = ((size_t)n * TT + r) * DD;
    size_t ob1 = ((size_t)n * TT + r + 8) * DD;
#pragma unroll
    for (int nt = 0; nt < 8; nt++) {
        int off = h * SS + (nt >> 1) * 16 + 2 * (2 * la3 + (nt & 1));
        *(uint32_t*)&g_Oh[ob0 + off] = h2u(o[nt][0] * i0, o[nt][1] * i0);
        *(uint32_t*)&g_Oh[ob1 + off] = h2u(o[nt][2] * i1, o[nt][3] * i1);
    }
}

// ============================================================================
// Launch
// ============================================================================
extern "C" void kernel_launch(void* const* d_in, const int* in_sizes, int n_in,
                              void* d_out, int out_size)
{
    const float* qseq = (const float*)d_in[0];
    const float* rseq = (const float*)d_in[1];
    const float* mask = (const float*)d_in[2];
    const float* Wq   = (const float*)d_in[3];
    const float* Wk   = (const float*)d_in[4];
    const float* Wv   = (const float*)d_in[5];
    const float* Wo   = (const float*)d_in[6];
    float* out = (float*)d_out;

    cudaFuncSetAttribute(gemm_f16_kernel, cudaFuncAttributeMaxDynamicSharedMemorySize,
                         GEMM_SMEM);
    cudaFuncSetAttribute(flash_kernel, cudaFuncAttributeMaxDynamicSharedMemorySize,
                         FLASH_SMEM);

    // Prep: f32 -> packed fp16
    prep_act<<<dim3(1024, 1, 2), 256>>>(qseq, rseq);
    prep_w<<<dim3(256, 1, 4), 256>>>(Wq, Wk, Wv, Wo);

    // QKV projections fused into one launch over z
    gemm_f16_kernel<<<dim3(8, 32, 3), 256, GEMM_SMEM>>>(nullptr, 0);

    // Flash attention
    flash_kernel<<<dim3(16, HH, NB), 256, FLASH_SMEM>>>(mask);

    // Output projection -> d_out
    gemm_f16_kernel<<<dim3(8, 32, 1), 256, GEMM_SMEM>>>(out, 1);
}